// round 1
// baseline (speedup 1.0000x reference)
#include <cuda_runtime.h>
#include <math.h>

#define T_TOK 32768
#define CDIM  512
#define NE    8
#define NH    16

// ---------------- scratch (device globals; no allocation) ----------------
__device__ float g_h [T_TOK * CDIM];   // gate pre-BN activations
__device__ float g_of[T_TOK * CDIM];   // out_flat accumulator (token-major)
__device__ float g_sum[CDIM];
__device__ float g_sumsq[CDIM];
__device__ float g_scale[CDIM];        // gamma*rstd
__device__ float g_shift[CDIM];        // beta - gamma*rstd*mu
__device__ float g_usage[NE];
__device__ int   g_te[T_TOK * 2];      // top-2 expert ids per token
__device__ float g_tw[T_TOK * 2];      // top-2 softmax weights per token

// ---------------- zero scratch ----------------
__global__ void k_zero() {
    int i = blockIdx.x * blockDim.x + threadIdx.x;
    float4 z = make_float4(0.f, 0.f, 0.f, 0.f);
    for (int idx = i; idx < T_TOK * CDIM / 4; idx += gridDim.x * blockDim.x)
        ((float4*)g_of)[idx] = z;
    if (blockIdx.x == 0) {
        if (threadIdx.x < CDIM) { g_sum[threadIdx.x] = 0.f; g_sumsq[threadIdx.x] = 0.f; }
        if (threadIdx.x < NE)   g_usage[threadIdx.x] = 0.f;
    }
}

// ---------------- gate GEMM: h = X @ Wg1^T + bg1 ----------------
// X[T,512] row-major, W[512out,512in] row-major -> NT GEMM, both K-contiguous.
// 128x128 tile, BK=16, 256 threads, 8x8 micro-tile.
__global__ __launch_bounds__(256) void k_gemm(const float* __restrict__ X,
                                              const float* __restrict__ W,
                                              const float* __restrict__ bias) {
    __shared__ float As[16][128];
    __shared__ float Bs[16][128];
    const int m0 = blockIdx.x * 128;
    const int n0 = blockIdx.y * 128;
    const int tid = threadIdx.x;
    const int tx = tid & 15, ty = tid >> 4;
    const int lm = tid >> 1;           // 0..127 (tile row to load)
    const int koff = (tid & 1) * 8;    // 0 or 8 within BK
    const float* Ap = X + (size_t)(m0 + lm) * CDIM + koff;
    const float* Bp = W + (size_t)(n0 + lm) * CDIM + koff;

    float acc[8][8];
#pragma unroll
    for (int i = 0; i < 8; i++)
#pragma unroll
        for (int j = 0; j < 8; j++) acc[i][j] = 0.f;

    for (int kb = 0; kb < CDIM; kb += 16) {
        float4 a0 = *(const float4*)(Ap + kb);
        float4 a1 = *(const float4*)(Ap + kb + 4);
        float4 b0 = *(const float4*)(Bp + kb);
        float4 b1 = *(const float4*)(Bp + kb + 4);
        __syncthreads();
        As[koff + 0][lm] = a0.x; As[koff + 1][lm] = a0.y;
        As[koff + 2][lm] = a0.z; As[koff + 3][lm] = a0.w;
        As[koff + 4][lm] = a1.x; As[koff + 5][lm] = a1.y;
        As[koff + 6][lm] = a1.z; As[koff + 7][lm] = a1.w;
        Bs[koff + 0][lm] = b0.x; Bs[koff + 1][lm] = b0.y;
        Bs[koff + 2][lm] = b0.z; Bs[koff + 3][lm] = b0.w;
        Bs[koff + 4][lm] = b1.x; Bs[koff + 5][lm] = b1.y;
        Bs[koff + 6][lm] = b1.z; Bs[koff + 7][lm] = b1.w;
        __syncthreads();
#pragma unroll
        for (int k = 0; k < 16; k++) {
            float ar[8], br[8];
            *(float4*)(ar)     = *(const float4*)(&As[k][ty * 8]);
            *(float4*)(ar + 4) = *(const float4*)(&As[k][ty * 8 + 4]);
            *(float4*)(br)     = *(const float4*)(&Bs[k][tx * 8]);
            *(float4*)(br + 4) = *(const float4*)(&Bs[k][tx * 8 + 4]);
#pragma unroll
            for (int i = 0; i < 8; i++)
#pragma unroll
                for (int j = 0; j < 8; j++)
                    acc[i][j] = fmaf(ar[i], br[j], acc[i][j]);
        }
    }
    float bv[8];
#pragma unroll
    for (int j = 0; j < 8; j++) bv[j] = bias[n0 + tx * 8 + j];
#pragma unroll
    for (int i = 0; i < 8; i++) {
        float* op = g_h + (size_t)(m0 + ty * 8 + i) * CDIM + n0 + tx * 8;
        float4 v0 = make_float4(acc[i][0] + bv[0], acc[i][1] + bv[1],
                                acc[i][2] + bv[2], acc[i][3] + bv[3]);
        float4 v1 = make_float4(acc[i][4] + bv[4], acc[i][5] + bv[5],
                                acc[i][6] + bv[6], acc[i][7] + bv[7]);
        *(float4*)op = v0; *(float4*)(op + 4) = v1;
    }
}

// ---------------- per-channel BN statistics ----------------
__global__ void k_stats() {
    int c = threadIdx.x;                 // 512 threads
    int r0 = blockIdx.x * 256;           // 128 blocks x 256 rows
    float s = 0.f, s2 = 0.f;
    for (int r = 0; r < 256; r++) {
        float v = g_h[(size_t)(r0 + r) * CDIM + c];
        s += v; s2 = fmaf(v, v, s2);
    }
    atomicAdd(&g_sum[c], s);
    atomicAdd(&g_sumsq[c], s2);
}

__global__ void k_finalize(const float* __restrict__ gamma, const float* __restrict__ beta) {
    int c = threadIdx.x;
    float mu  = g_sum[c] * (1.f / T_TOK);
    float var = g_sumsq[c] * (1.f / T_TOK) - mu * mu;   // biased var (matches BN)
    float rstd = rsqrtf(var + 1e-5f);
    float sc = gamma[c] * rstd;
    g_scale[c] = sc;
    g_shift[c] = beta[c] - sc * mu;
}

// ---------------- routing: normalize+relu -> logits -> top2 softmax ----------------
__global__ __launch_bounds__(256) void k_route(const float* __restrict__ wg2,
                                               const float* __restrict__ bg2) {
    __shared__ float w2s[NE * CDIM];
    __shared__ float scs[CDIM], shs[CDIM];
    __shared__ float s_us[NE];
    int tid = threadIdx.x;
    for (int i = tid; i < NE * CDIM; i += 256) w2s[i] = wg2[i];
    for (int i = tid; i < CDIM; i += 256) { scs[i] = g_scale[i]; shs[i] = g_shift[i]; }
    if (tid < NE) s_us[tid] = 0.f;
    __syncthreads();

    int warp = tid >> 5, lane = tid & 31;
    int tbase = blockIdx.x * 256 + warp * 32;
    for (int it = 0; it < 32; it++) {
        int t = tbase + it;
        const float* hp = g_h + (size_t)t * CDIM;
        float acc[NE];
#pragma unroll
        for (int e = 0; e < NE; e++) acc[e] = 0.f;
#pragma unroll
        for (int i = 0; i < 16; i++) {
            int c = lane + 32 * i;
            float hn = fmaxf(fmaf(hp[c], scs[c], shs[c]), 0.f);
#pragma unroll
            for (int e = 0; e < NE; e++) acc[e] = fmaf(hn, w2s[e * CDIM + c], acc[e]);
        }
#pragma unroll
        for (int e = 0; e < NE; e++)
#pragma unroll
            for (int off = 16; off > 0; off >>= 1)
                acc[e] += __shfl_xor_sync(0xffffffffu, acc[e], off);
        if (lane == 0) {
            float lg[NE];
#pragma unroll
            for (int e = 0; e < NE; e++) lg[e] = acc[e] + bg2[e];
            int i1 = 0; float v1 = lg[0];
#pragma unroll
            for (int e = 1; e < NE; e++) if (lg[e] > v1) { v1 = lg[e]; i1 = e; }
            int i2 = (i1 == 0) ? 1 : 0; float v2 = lg[i2];
#pragma unroll
            for (int e = 0; e < NE; e++)
                if (e != i1 && lg[e] > v2) { v2 = lg[e]; i2 = e; }
            float ew = expf(v2 - v1);
            float inv = 1.f / (1.f + ew);
            float wa = inv, wb = ew * inv;
            g_te[t * 2] = i1; g_te[t * 2 + 1] = i2;
            g_tw[t * 2] = wa; g_tw[t * 2 + 1] = wb;
            atomicAdd(&s_us[i1], wa);
            atomicAdd(&s_us[i2], wb);
        }
    }
    __syncthreads();
    if (tid < NE) atomicAdd(&g_usage[tid], s_us[tid]);
}

// ---------------- expert compute (top-2 only) ----------------
// grid (token_chunks=128, experts=8). Block stages w1[e], w2[e] in SMEM,
// compacts its 256-token chunk to tokens routed to e (~64 avg), processes
// in waves of 64 with x rows staged in SMEM, RED-adds into g_of.
__global__ __launch_bounds__(256) void k_expert(const float* __restrict__ X,
                                                const float* __restrict__ w1,
                                                const float* __restrict__ b1,
                                                const float* __restrict__ w2,
                                                const float* __restrict__ b2) {
    extern __shared__ float sm[];
    float* w1s = sm;                       // 512*16
    float* w2s = w1s + CDIM * NH;          // 16*512
    float* b2s = w2s + NH * CDIM;          // 512
    float* b1s = b2s + CDIM;               // 16
    float* h1s = b1s + NH;                 // 64*16
    float* wts = h1s + 64 * NH;            // 256
    float* xs  = wts + 256;                // 64*516 (padded rows)
    int*   toks = (int*)(xs + 64 * 516);   // 256
    __shared__ int s_cnt;

    int e = blockIdx.y;
    int tid = threadIdx.x;
    const float* w1p = w1 + (size_t)e * CDIM * NH;
    const float* w2p = w2 + (size_t)e * NH * CDIM;
    for (int i = tid; i < CDIM * NH; i += 256) { w1s[i] = w1p[i]; w2s[i] = w2p[i]; }
    for (int i = tid; i < CDIM; i += 256) b2s[i] = b2[e * CDIM + i];
    if (tid < NH) b1s[tid] = b1[e * NH + tid];
    if (tid == 0) s_cnt = 0;
    __syncthreads();

    // compact this chunk's tokens routed to expert e
    {
        int t = blockIdx.x * 256 + tid;
        int e1 = g_te[t * 2], e2 = g_te[t * 2 + 1];
        float w = (e1 == e) ? g_tw[t * 2] : ((e2 == e) ? g_tw[t * 2 + 1] : -1.f);
        if (w >= 0.f) {
            int p = atomicAdd(&s_cnt, 1);
            toks[p] = t; wts[p] = w;
        }
    }
    __syncthreads();
    int nact = s_cnt;

    for (int base = 0; base < nact; base += 64) {
        int nb = min(64, nact - base);
        // stage x rows
        for (int idx = tid; idx < nb * 128; idx += 256) {
            int r = idx >> 7, q = idx & 127;
            float4 v = *(const float4*)(X + (size_t)toks[base + r] * CDIM + q * 4);
            *(float4*)(xs + r * 516 + q * 4) = v;
        }
        __syncthreads();
        // phase 1: h1 = relu(x @ w1 + b1), thread=(token, 4 h-cols)
        {
            int tl = tid >> 2;
            int hq = (tid & 3) * 4;
            if (tl < nb) {
                float a0 = b1s[hq], a1 = b1s[hq + 1], a2 = b1s[hq + 2], a3 = b1s[hq + 3];
                const float* xr = xs + tl * 516;
#pragma unroll 4
                for (int k = 0; k < CDIM; k++) {
                    float xv = xr[k];
                    float4 w = *(const float4*)(w1s + k * NH + hq);
                    a0 = fmaf(xv, w.x, a0); a1 = fmaf(xv, w.y, a1);
                    a2 = fmaf(xv, w.z, a2); a3 = fmaf(xv, w.w, a3);
                }
                h1s[tl * NH + hq]     = fmaxf(a0, 0.f);
                h1s[tl * NH + hq + 1] = fmaxf(a1, 0.f);
                h1s[tl * NH + hq + 2] = fmaxf(a2, 0.f);
                h1s[tl * NH + hq + 3] = fmaxf(a3, 0.f);
            }
        }
        __syncthreads();
        // phase 2: out += wt * (h1 @ w2 + b2)
        for (int tl = 0; tl < nb; tl++) {
            int tok = toks[base + tl];
            float wt = wts[base + tl];
            float hv[NH];
#pragma unroll
            for (int h = 0; h < NH; h++) hv[h] = h1s[tl * NH + h];
#pragma unroll
            for (int cc = 0; cc < 2; cc++) {
                int c = tid + cc * 256;
                float accv = b2s[c];
#pragma unroll
                for (int h = 0; h < NH; h++)
                    accv = fmaf(hv[h], w2s[h * CDIM + c], accv);
                atomicAdd(&g_of[(size_t)tok * CDIM + c], wt * accv);
            }
        }
        __syncthreads();
    }
}

// ---------------- transpose out_flat [B*N, C] -> out [B, C, N] ----------------
__global__ void k_transpose(float* __restrict__ out) {
    __shared__ float tile[32][33];
    int b = blockIdx.z;
    int n0 = blockIdx.x * 32, c0 = blockIdx.y * 32;
    int tx = threadIdx.x, ty = threadIdx.y;     // 32 x 8
#pragma unroll
    for (int i = 0; i < 4; i++) {
        int n = n0 + ty + i * 8;
        tile[ty + i * 8][tx] = g_of[(size_t)(b * 4096 + n) * CDIM + c0 + tx];
    }
    __syncthreads();
#pragma unroll
    for (int i = 0; i < 4; i++) {
        int c = c0 + ty + i * 8;
        out[(size_t)(b * CDIM + c) * 4096 + n0 + tx] = tile[tx][ty + i * 8];
    }
}

// ---------------- load-balance loss ----------------
__global__ void k_lb(float* __restrict__ out, int out_size) {
    float lb = 0.f;
    for (int e = 0; e < NE; e++) {
        float u = g_usage[e] * (1.f / T_TOK);
        lb += u * u;
    }
    lb *= (float)NE;
    if (out_size > T_TOK * CDIM) out[T_TOK * CDIM] = lb;
}

// ---------------- launcher ----------------
extern "C" void kernel_launch(void* const* d_in, const int* in_sizes, int n_in,
                              void* d_out, int out_size) {
    const float* x     = (const float*)d_in[0];
    const float* wg1   = (const float*)d_in[1];
    const float* bg1   = (const float*)d_in[2];
    const float* gamma = (const float*)d_in[3];
    const float* beta  = (const float*)d_in[4];
    const float* wg2   = (const float*)d_in[5];
    const float* bg2   = (const float*)d_in[6];
    const float* w1    = (const float*)d_in[7];
    const float* b1    = (const float*)d_in[8];
    const float* w2    = (const float*)d_in[9];
    const float* b2    = (const float*)d_in[10];
    float* out = (float*)d_out;

    k_zero<<<2048, 512>>>();
    k_gemm<<<dim3(256, 4), 256>>>(x, wg1, bg1);
    k_stats<<<128, 512>>>();
    k_finalize<<<1, 512>>>(gamma, beta);
    k_route<<<128, 256>>>(wg2, bg2);

    int smem_bytes = (CDIM * NH + NH * CDIM + CDIM + NH + 64 * NH + 256 + 64 * 516) * 4
                     + 256 * 4;  // + toks
    cudaFuncSetAttribute(k_expert, cudaFuncAttributeMaxDynamicSharedMemorySize, smem_bytes);
    k_expert<<<dim3(128, NE), 256, smem_bytes>>>(x, w1, b1, w2, b2);

    k_transpose<<<dim3(128, 16, 8), dim3(32, 8)>>>(out);
    k_lb<<<1, 1>>>(out, out_size);
}

// round 3
// speedup vs baseline: 1.1584x; 1.1584x over previous
#include <cuda_runtime.h>
#include <math.h>
#include <stdint.h>

#define T_TOK 32768
#define CDIM  512
#define NE    8
#define NH    16

// GEMM tiling
#define BM 128
#define BN 256
#define BK 32
#define PAD 36                      // words per row in smem tile
#define A_WORDS (BM * PAD)          // 4608
#define B_WORDS (BN * PAD)          // 9216
#define STAGE_WORDS (2 * A_WORDS + 2 * B_WORDS)  // 27648 words = 110592 B
#define NSTAGE 16                   // K=512 / BK

// ---------------- scratch (device globals; no allocation) ----------------
__device__ float g_h [T_TOK * CDIM];     // gate pre-BN activations
__device__ float g_of[T_TOK * CDIM];     // out_flat accumulator (token-major)
__device__ float g_sum[CDIM];
__device__ float g_sumsq[CDIM];
__device__ float g_scale[CDIM];
__device__ float g_shift[CDIM];
__device__ float g_usage[NE];
__device__ int   g_te[T_TOK * 2];
__device__ float g_tw[T_TOK * 2];

// ---------------- helpers ----------------
static __device__ __forceinline__ float tf32r(float x) {
    uint32_t u; asm("cvt.rna.tf32.f32 %0, %1;" : "=r"(u) : "f"(x));
    return __uint_as_float(u);
}
static __device__ __forceinline__ void mma_tf32(float* d, const uint32_t* a, const uint32_t* b) {
    asm volatile("mma.sync.aligned.m16n8k8.row.col.f32.tf32.tf32.f32 "
        "{%0,%1,%2,%3},{%4,%5,%6,%7},{%8,%9},{%0,%1,%2,%3};"
        : "+f"(d[0]), "+f"(d[1]), "+f"(d[2]), "+f"(d[3])
        : "r"(a[0]), "r"(a[1]), "r"(a[2]), "r"(a[3]), "r"(b[0]), "r"(b[1]));
}

// ---------------- zero scratch ----------------
__global__ void k_zero() {
    int i = blockIdx.x * blockDim.x + threadIdx.x;
    float4 z = make_float4(0.f, 0.f, 0.f, 0.f);
    for (int idx = i; idx < T_TOK * CDIM / 4; idx += gridDim.x * blockDim.x)
        ((float4*)g_of)[idx] = z;
    if (blockIdx.x == 0) {
        if (threadIdx.x < CDIM) { g_sum[threadIdx.x] = 0.f; g_sumsq[threadIdx.x] = 0.f; }
        if (threadIdx.x < NE)   g_usage[threadIdx.x] = 0.f;
    }
}

// ---------------- 3xTF32 mma.sync GEMM: h = X @ Wg1^T + bg1 ----------------
// grid (256, 2), 256 threads = 8 warps (2m x 4n), warp tile 64x64, acc 128 regs.
// smem per stage: Ah[128][36] Al[128][36] Bh[256][36] Bl[256][36] (hi/lo tf32 split)
__global__ __launch_bounds__(256, 1) void k_gemm_mma(const float* __restrict__ X,
                                                     const float* __restrict__ W,
                                                     const float* __restrict__ bias) {
    extern __shared__ float sm[];
    const int m0 = blockIdx.x * BM;
    const int n0 = blockIdx.y * BN;
    const int tid = threadIdx.x;
    const int lane = tid & 31;
    const int wid = tid >> 5;
    const int wm = (wid & 1) * 64;
    const int wn = (wid >> 1) * 64;

    const int lrow = tid >> 3;        // 0..31 loader row base
    const int lk4  = tid & 7;         // float4 index within 32-k

    const float* Abase = X + (size_t)(m0 + lrow) * CDIM + lk4 * 4;
    const float* Bbase = W + (size_t)(n0 + lrow) * CDIM + lk4 * 4;

    float acc[4][8][4];
#pragma unroll
    for (int mt = 0; mt < 4; mt++)
#pragma unroll
        for (int nt = 0; nt < 8; nt++)
#pragma unroll
            for (int q = 0; q < 4; q++) acc[mt][nt][q] = 0.f;

    float4 pa[4], pb[8];

    // prologue: stage 0 ldg
#pragma unroll
    for (int i = 0; i < 4; i++) pa[i] = *(const float4*)(Abase + (size_t)(32 * i) * CDIM);
#pragma unroll
    for (int i = 0; i < 8; i++) pb[i] = *(const float4*)(Bbase + (size_t)(32 * i) * CDIM);

    for (int s = 0; s < NSTAGE; s++) {
        float* sb = sm + (s & 1) * STAGE_WORDS;
        // store prefetched stage s (split hi/lo)
        {
            float* ah = sb;
            float* al = sb + A_WORDS;
            float* bh = sb + 2 * A_WORDS;
            float* bl = sb + 2 * A_WORDS + B_WORDS;
#pragma unroll
            for (int i = 0; i < 4; i++) {
                float4 v = pa[i];
                float4 hi, lo;
                hi.x = tf32r(v.x); lo.x = tf32r(v.x - hi.x);
                hi.y = tf32r(v.y); lo.y = tf32r(v.y - hi.y);
                hi.z = tf32r(v.z); lo.z = tf32r(v.z - hi.z);
                hi.w = tf32r(v.w); lo.w = tf32r(v.w - hi.w);
                int off = (lrow + 32 * i) * PAD + lk4 * 4;
                *(float4*)(ah + off) = hi;
                *(float4*)(al + off) = lo;
            }
#pragma unroll
            for (int i = 0; i < 8; i++) {
                float4 v = pb[i];
                float4 hi, lo;
                hi.x = tf32r(v.x); lo.x = tf32r(v.x - hi.x);
                hi.y = tf32r(v.y); lo.y = tf32r(v.y - hi.y);
                hi.z = tf32r(v.z); lo.z = tf32r(v.z - hi.z);
                hi.w = tf32r(v.w); lo.w = tf32r(v.w - hi.w);
                int off = (lrow + 32 * i) * PAD + lk4 * 4;
                *(float4*)(bh + off) = hi;
                *(float4*)(bl + off) = lo;
            }
        }
        __syncthreads();
        // issue ldg for stage s+1 (overlaps with compute below)
        if (s + 1 < NSTAGE) {
            const float* An = Abase + (s + 1) * BK;
            const float* Bn = Bbase + (s + 1) * BK;
#pragma unroll
            for (int i = 0; i < 4; i++) pa[i] = *(const float4*)(An + (size_t)(32 * i) * CDIM);
#pragma unroll
            for (int i = 0; i < 8; i++) pb[i] = *(const float4*)(Bn + (size_t)(32 * i) * CDIM);
        }

        // compute 4 k8-steps from stage s
        const uint32_t* ah = (const uint32_t*)sb;
        const uint32_t* al = (const uint32_t*)(sb + A_WORDS);
        const uint32_t* bhp = (const uint32_t*)(sb + 2 * A_WORDS);
        const uint32_t* blp = (const uint32_t*)(sb + 2 * A_WORDS + B_WORDS);
        const int lr = lane >> 2;      // 0..7
        const int lc = lane & 3;       // 0..3
#pragma unroll
        for (int k8 = 0; k8 < 4; k8++) {
            const int k0 = k8 * 8 + lc;
            uint32_t afh[4][4], afl[4][4];
#pragma unroll
            for (int mt = 0; mt < 4; mt++) {
                int m = wm + mt * 16 + lr;
                afh[mt][0] = ah[m * PAD + k0];
                afh[mt][1] = ah[(m + 8) * PAD + k0];
                afh[mt][2] = ah[m * PAD + k0 + 4];
                afh[mt][3] = ah[(m + 8) * PAD + k0 + 4];
                afl[mt][0] = al[m * PAD + k0];
                afl[mt][1] = al[(m + 8) * PAD + k0];
                afl[mt][2] = al[m * PAD + k0 + 4];
                afl[mt][3] = al[(m + 8) * PAD + k0 + 4];
            }
#pragma unroll
            for (int nt = 0; nt < 8; nt++) {
                int n = wn + nt * 8 + lr;
                uint32_t bfh[2], bfl[2];
                bfh[0] = bhp[n * PAD + k0];
                bfh[1] = bhp[n * PAD + k0 + 4];
                bfl[0] = blp[n * PAD + k0];
                bfl[1] = blp[n * PAD + k0 + 4];
#pragma unroll
                for (int mt = 0; mt < 4; mt++) {
                    mma_tf32(acc[mt][nt], afh[mt], bfh);
                    mma_tf32(acc[mt][nt], afh[mt], bfl);
                    mma_tf32(acc[mt][nt], afl[mt], bfh);
                }
            }
        }
        __syncthreads();
    }

    // epilogue: add bias, write g_h
    const int lr = lane >> 2, lc = lane & 3;
#pragma unroll
    for (int nt = 0; nt < 8; nt++) {
        int col = n0 + wn + nt * 8 + lc * 2;
        float b0 = __ldg(bias + col), b1 = __ldg(bias + col + 1);
#pragma unroll
        for (int mt = 0; mt < 4; mt++) {
            int row = m0 + wm + mt * 16 + lr;
            float2 v0 = make_float2(acc[mt][nt][0] + b0, acc[mt][nt][1] + b1);
            float2 v1 = make_float2(acc[mt][nt][2] + b0, acc[mt][nt][3] + b1);
            *(float2*)(g_h + (size_t)row * CDIM + col) = v0;
            *(float2*)(g_h + (size_t)(row + 8) * CDIM + col) = v1;
        }
    }
}

// ---------------- per-channel BN statistics ----------------
__global__ void k_stats() {
    int c = threadIdx.x;
    int r0 = blockIdx.x * 256;
    float s = 0.f, s2 = 0.f;
    for (int r = 0; r < 256; r++) {
        float v = g_h[(size_t)(r0 + r) * CDIM + c];
        s += v; s2 = fmaf(v, v, s2);
    }
    atomicAdd(&g_sum[c], s);
    atomicAdd(&g_sumsq[c], s2);
}

__global__ void k_finalize(const float* __restrict__ gamma, const float* __restrict__ beta) {
    int c = threadIdx.x;
    float mu  = g_sum[c] * (1.f / T_TOK);
    float var = g_sumsq[c] * (1.f / T_TOK) - mu * mu;
    float rstd = rsqrtf(var + 1e-5f);
    float sc = gamma[c] * rstd;
    g_scale[c] = sc;
    g_shift[c] = beta[c] - sc * mu;
}

// ---------------- routing ----------------
__global__ __launch_bounds__(256) void k_route(const float* __restrict__ wg2,
                                               const float* __restrict__ bg2) {
    __shared__ float w2s[NE * CDIM];
    __shared__ float scs[CDIM], shs[CDIM];
    __shared__ float s_us[NE];
    int tid = threadIdx.x;
    for (int i = tid; i < NE * CDIM; i += 256) w2s[i] = wg2[i];
    for (int i = tid; i < CDIM; i += 256) { scs[i] = g_scale[i]; shs[i] = g_shift[i]; }
    if (tid < NE) s_us[tid] = 0.f;
    __syncthreads();

    int warp = tid >> 5, lane = tid & 31;
    int tbase = blockIdx.x * 256 + warp * 32;
    for (int it = 0; it < 32; it++) {
        int t = tbase + it;
        const float* hp = g_h + (size_t)t * CDIM;
        float acc[NE];
#pragma unroll
        for (int e = 0; e < NE; e++) acc[e] = 0.f;
#pragma unroll
        for (int i = 0; i < 16; i++) {
            int c = lane + 32 * i;
            float hn = fmaxf(fmaf(hp[c], scs[c], shs[c]), 0.f);
#pragma unroll
            for (int e = 0; e < NE; e++) acc[e] = fmaf(hn, w2s[e * CDIM + c], acc[e]);
        }
#pragma unroll
        for (int e = 0; e < NE; e++)
#pragma unroll
            for (int off = 16; off > 0; off >>= 1)
                acc[e] += __shfl_xor_sync(0xffffffffu, acc[e], off);
        if (lane == 0) {
            float lg[NE];
#pragma unroll
            for (int e = 0; e < NE; e++) lg[e] = acc[e] + bg2[e];
            int i1 = 0; float v1 = lg[0];
#pragma unroll
            for (int e = 1; e < NE; e++) if (lg[e] > v1) { v1 = lg[e]; i1 = e; }
            int i2 = (i1 == 0) ? 1 : 0; float v2 = lg[i2];
#pragma unroll
            for (int e = 0; e < NE; e++)
                if (e != i1 && lg[e] > v2) { v2 = lg[e]; i2 = e; }
            float ew = expf(v2 - v1);
            float inv = 1.f / (1.f + ew);
            float wa = inv, wb = ew * inv;
            g_te[t * 2] = i1; g_te[t * 2 + 1] = i2;
            g_tw[t * 2] = wa; g_tw[t * 2 + 1] = wb;
            atomicAdd(&s_us[i1], wa);
            atomicAdd(&s_us[i2], wb);
        }
    }
    __syncthreads();
    if (tid < NE) atomicAdd(&g_usage[tid], s_us[tid]);
}

// ---------------- expert compute (top-2 only) ----------------
__global__ __launch_bounds__(256) void k_expert(const float* __restrict__ X,
                                                const float* __restrict__ w1,
                                                const float* __restrict__ b1,
                                                const float* __restrict__ w2,
                                                const float* __restrict__ b2) {
    extern __shared__ float smx[];
    float* w1s = smx;
    float* w2s = w1s + CDIM * NH;
    float* b2s = w2s + NH * CDIM;
    float* b1s = b2s + CDIM;
    float* h1s = b1s + NH;
    float* wts = h1s + 64 * NH;
    float* xs  = wts + 256;
    int*   toks = (int*)(xs + 64 * 516);
    __shared__ int s_cnt;

    int e = blockIdx.y;
    int tid = threadIdx.x;
    const float* w1p = w1 + (size_t)e * CDIM * NH;
    const float* w2p = w2 + (size_t)e * NH * CDIM;
    for (int i = tid; i < CDIM * NH; i += 256) { w1s[i] = w1p[i]; w2s[i] = w2p[i]; }
    for (int i = tid; i < CDIM; i += 256) b2s[i] = b2[e * CDIM + i];
    if (tid < NH) b1s[tid] = b1[e * NH + tid];
    if (tid == 0) s_cnt = 0;
    __syncthreads();

    {
        int t = blockIdx.x * 256 + tid;
        int e1 = g_te[t * 2], e2 = g_te[t * 2 + 1];
        float w = (e1 == e) ? g_tw[t * 2] : ((e2 == e) ? g_tw[t * 2 + 1] : -1.f);
        if (w >= 0.f) {
            int p = atomicAdd(&s_cnt, 1);
            toks[p] = t; wts[p] = w;
        }
    }
    __syncthreads();
    int nact = s_cnt;

    for (int bb = 0; bb < nact; bb += 64) {
        int nb = min(64, nact - bb);
        for (int idx = tid; idx < nb * 128; idx += 256) {
            int r = idx >> 7, q = idx & 127;
            float4 v = *(const float4*)(X + (size_t)toks[bb + r] * CDIM + q * 4);
            *(float4*)(xs + r * 516 + q * 4) = v;
        }
        __syncthreads();
        {
            int tl = tid >> 2;
            int hq = (tid & 3) * 4;
            if (tl < nb) {
                float a0 = b1s[hq], a1 = b1s[hq + 1], a2 = b1s[hq + 2], a3 = b1s[hq + 3];
                const float* xr = xs + tl * 516;
#pragma unroll 4
                for (int k = 0; k < CDIM; k++) {
                    float xv = xr[k];
                    float4 w = *(const float4*)(w1s + k * NH + hq);
                    a0 = fmaf(xv, w.x, a0); a1 = fmaf(xv, w.y, a1);
                    a2 = fmaf(xv, w.z, a2); a3 = fmaf(xv, w.w, a3);
                }
                h1s[tl * NH + hq]     = fmaxf(a0, 0.f);
                h1s[tl * NH + hq + 1] = fmaxf(a1, 0.f);
                h1s[tl * NH + hq + 2] = fmaxf(a2, 0.f);
                h1s[tl * NH + hq + 3] = fmaxf(a3, 0.f);
            }
        }
        __syncthreads();
        for (int tl = 0; tl < nb; tl++) {
            int tok = toks[bb + tl];
            float wt = wts[bb + tl];
            float hv[NH];
#pragma unroll
            for (int h = 0; h < NH; h++) hv[h] = h1s[tl * NH + h];
#pragma unroll
            for (int cc = 0; cc < 2; cc++) {
                int c = tid + cc * 256;
                float accv = b2s[c];
#pragma unroll
                for (int h = 0; h < NH; h++)
                    accv = fmaf(hv[h], w2s[h * CDIM + c], accv);
                atomicAdd(&g_of[(size_t)tok * CDIM + c], wt * accv);
            }
        }
        __syncthreads();
    }
}

// ---------------- transpose ----------------
__global__ void k_transpose(float* __restrict__ out) {
    __shared__ float tile[32][33];
    int b = blockIdx.z;
    int n0 = blockIdx.x * 32, c0 = blockIdx.y * 32;
    int tx = threadIdx.x, ty = threadIdx.y;
#pragma unroll
    for (int i = 0; i < 4; i++) {
        int n = n0 + ty + i * 8;
        tile[ty + i * 8][tx] = g_of[(size_t)(b * 4096 + n) * CDIM + c0 + tx];
    }
    __syncthreads();
#pragma unroll
    for (int i = 0; i < 4; i++) {
        int c = c0 + ty + i * 8;
        out[(size_t)(b * CDIM + c) * 4096 + n0 + tx] = tile[tx][ty + i * 8];
    }
}

// ---------------- load-balance loss ----------------
__global__ void k_lb(float* __restrict__ out, int out_size) {
    float lb = 0.f;
    for (int e = 0; e < NE; e++) {
        float u = g_usage[e] * (1.f / T_TOK);
        lb += u * u;
    }
    lb *= (float)NE;
    if (out_size > T_TOK * CDIM) out[T_TOK * CDIM] = lb;
}

// ---------------- launcher ----------------
extern "C" void kernel_launch(void* const* d_in, const int* in_sizes, int n_in,
                              void* d_out, int out_size) {
    const float* x     = (const float*)d_in[0];
    const float* wg1   = (const float*)d_in[1];
    const float* bg1   = (const float*)d_in[2];
    const float* gamma = (const float*)d_in[3];
    const float* beta  = (const float*)d_in[4];
    const float* wg2   = (const float*)d_in[5];
    const float* bg2   = (const float*)d_in[6];
    const float* w1    = (const float*)d_in[7];
    const float* b1    = (const float*)d_in[8];
    const float* w2    = (const float*)d_in[9];
    const float* b2    = (const float*)d_in[10];
    float* out = (float*)d_out;

    k_zero<<<2048, 512>>>();

    int gemm_smem = 2 * STAGE_WORDS * 4;   // 221184 B
    cudaFuncSetAttribute(k_gemm_mma, cudaFuncAttributeMaxDynamicSharedMemorySize, gemm_smem);
    k_gemm_mma<<<dim3(T_TOK / BM, CDIM / BN), 256, gemm_smem>>>(x, wg1, bg1);

    k_stats<<<128, 512>>>();
    k_finalize<<<1, 512>>>(gamma, beta);
    k_route<<<128, 256>>>(wg2, bg2);

    int smem_bytes = (CDIM * NH + NH * CDIM + CDIM + NH + 64 * NH + 256 + 64 * 516) * 4 + 256 * 4;
    cudaFuncSetAttribute(k_expert, cudaFuncAttributeMaxDynamicSharedMemorySize, smem_bytes);
    k_expert<<<dim3(128, NE), 256, smem_bytes>>>(x, w1, b1, w2, b2);

    k_transpose<<<dim3(128, 16, 8), dim3(32, 8)>>>(out);
    k_lb<<<1, 1>>>(out, out_size);
}

// round 4
// speedup vs baseline: 1.1866x; 1.0244x over previous
#include <cuda_runtime.h>
#include <cuda_fp16.h>
#include <math.h>
#include <stdint.h>

#define T_TOK 32768
#define CDIM  512
#define NE    8
#define NH    16

// GEMM tiling: CTA 128x256, BK=32, 512 threads (16 warps, warp tile 32x64)
#define BM 128
#define BN 256
#define BK 32
#define NSTAGE 16
// smem words (uint32 = fp16x2): Ah 128*16, Al 128*16, Bh 256*16, Bl 256*16
#define AW (BM * 16)                 // 2048
#define BW (BN * 16)                 // 4096
#define STAGE_WORDS (2 * AW + 2 * BW)  // 12288 words = 49152 B

// swizzled word index within a tile: row stride 16 words, XOR bits 2-3 by (row>>1)&3
#define SWZ(row, kw) (((row) << 4) + ((kw) ^ ((((row) >> 1) & 3) << 2)))

// ---------------- scratch ----------------
__device__ float g_h [T_TOK * CDIM];
__device__ float g_of[T_TOK * CDIM];
__device__ float g_sum[CDIM];
__device__ float g_sumsq[CDIM];
__device__ float g_scale[CDIM];
__device__ float g_shift[CDIM];
__device__ float g_usage[NE];
__device__ int   g_te[T_TOK * 2];
__device__ float g_tw[T_TOK * 2];

// ---------------- helpers ----------------
static __device__ __forceinline__ uint32_t pack2h(float x1, float x0) {
    uint32_t r;
    asm("cvt.rn.f16x2.f32 %0, %1, %2;" : "=r"(r) : "f"(x1), "f"(x0));
    return r;
}
// split float4 (scaled by sc) -> two hi words + two lo words
static __device__ __forceinline__ void split4(float4 v, float sc,
                                              uint32_t& h0, uint32_t& h1,
                                              uint32_t& l0, uint32_t& l1) {
    float a = v.x * sc, b = v.y * sc, c = v.z * sc, d = v.w * sc;
    h0 = pack2h(b, a);
    h1 = pack2h(d, c);
    __half2 ha = *(__half2*)&h0;
    __half2 hb = *(__half2*)&h1;
    float2 fa = __half22float2(ha);
    float2 fb = __half22float2(hb);
    l0 = pack2h(b - fa.y, a - fa.x);
    l1 = pack2h(d - fb.y, c - fb.x);
}
static __device__ __forceinline__ void mma_f16(float* d, const uint32_t* a, const uint32_t* b) {
    asm volatile("mma.sync.aligned.m16n8k16.row.col.f32.f16.f16.f32 "
        "{%0,%1,%2,%3},{%4,%5,%6,%7},{%8,%9},{%0,%1,%2,%3};"
        : "+f"(d[0]), "+f"(d[1]), "+f"(d[2]), "+f"(d[3])
        : "r"(a[0]), "r"(a[1]), "r"(a[2]), "r"(a[3]), "r"(b[0]), "r"(b[1]));
}

// ---------------- zero scratch ----------------
__global__ void k_zero() {
    int i = blockIdx.x * blockDim.x + threadIdx.x;
    float4 z = make_float4(0.f, 0.f, 0.f, 0.f);
    for (int idx = i; idx < T_TOK * CDIM / 4; idx += gridDim.x * blockDim.x)
        ((float4*)g_of)[idx] = z;
    if (blockIdx.x == 0) {
        if (threadIdx.x < CDIM) { g_sum[threadIdx.x] = 0.f; g_sumsq[threadIdx.x] = 0.f; }
        if (threadIdx.x < NE)   g_usage[threadIdx.x] = 0.f;
    }
}

// ---------------- 3xFP16 mma.sync GEMM + fused BN partial stats ----------------
// h = X @ Wg1^T + bg1 ; W pre-scaled by 64, acc scaled back by 1/64.
__global__ __launch_bounds__(512, 1) void k_gemm_mma(const float* __restrict__ X,
                                                     const float* __restrict__ W,
                                                     const float* __restrict__ bias) {
    extern __shared__ uint32_t sm[];
    const int m0 = blockIdx.x * BM;
    const int n0 = blockIdx.y * BN;
    const int tid = threadIdx.x;
    const int lane = tid & 31;
    const int wid = tid >> 5;
    const int wm = (wid & 3) * 32;       // warp m-offset (4 m-warps)
    const int wn = (wid >> 2) * 64;      // warp n-offset (4 n-warps)
    const int lr = lane >> 2, lc = lane & 3;

    // loader mapping
    const int arow = tid >> 2, aq = tid & 3;          // A: 128 rows x {aq, aq+4} float4
    const int brow = tid >> 1, bq = tid & 1;          // B: 256 rows x {bq, bq+2, bq+4, bq+6}
    const float* Aptr = X + (size_t)(m0 + arow) * CDIM + aq * 4;
    const float* Bptr = W + (size_t)(n0 + brow) * CDIM + bq * 4;

    float acc[2][8][4];
#pragma unroll
    for (int mt = 0; mt < 2; mt++)
#pragma unroll
        for (int nt = 0; nt < 8; nt++)
#pragma unroll
            for (int q = 0; q < 4; q++) acc[mt][nt][q] = 0.f;

    float4 pa[2], pb[4];
#pragma unroll
    for (int i = 0; i < 2; i++) pa[i] = *(const float4*)(Aptr + 16 * i);
#pragma unroll
    for (int i = 0; i < 4; i++) pb[i] = *(const float4*)(Bptr + 8 * i);

    for (int s = 0; s < NSTAGE; s++) {
        uint32_t* sb = sm + (s & 1) * STAGE_WORDS;
        uint32_t* Ah = sb;
        uint32_t* Al = sb + AW;
        uint32_t* Bh = sb + 2 * AW;
        uint32_t* Bl = sb + 2 * AW + BW;
        // split + store stage s
#pragma unroll
        for (int i = 0; i < 2; i++) {
            uint32_t h0, h1, l0, l1;
            split4(pa[i], 1.0f, h0, h1, l0, l1);
            int sw = SWZ(arow, 2 * (aq + 4 * i));
            *(uint2*)(Ah + sw) = make_uint2(h0, h1);
            *(uint2*)(Al + sw) = make_uint2(l0, l1);
        }
#pragma unroll
        for (int i = 0; i < 4; i++) {
            uint32_t h0, h1, l0, l1;
            split4(pb[i], 64.0f, h0, h1, l0, l1);
            int sw = SWZ(brow, 2 * (bq + 2 * i));
            *(uint2*)(Bh + sw) = make_uint2(h0, h1);
            *(uint2*)(Bl + sw) = make_uint2(l0, l1);
        }
        __syncthreads();
        if (s + 1 < NSTAGE) {
            const float* An = Aptr + (s + 1) * BK;
            const float* Bn = Bptr + (s + 1) * BK;
#pragma unroll
            for (int i = 0; i < 2; i++) pa[i] = *(const float4*)(An + 16 * i);
#pragma unroll
            for (int i = 0; i < 4; i++) pb[i] = *(const float4*)(Bn + 8 * i);
        }
        // compute: 2 k16-steps
#pragma unroll
        for (int h = 0; h < 2; h++) {
            const int kw0 = h * 8 + lc;
            uint32_t afh[2][4], afl[2][4];
#pragma unroll
            for (int mt = 0; mt < 2; mt++) {
                int m = wm + mt * 16 + lr;
                int i0 = SWZ(m, kw0),     i1 = SWZ(m + 8, kw0);
                int i2 = SWZ(m, kw0 + 4), i3 = SWZ(m + 8, kw0 + 4);
                afh[mt][0] = Ah[i0]; afh[mt][1] = Ah[i1];
                afh[mt][2] = Ah[i2]; afh[mt][3] = Ah[i3];
                afl[mt][0] = Al[i0]; afl[mt][1] = Al[i1];
                afl[mt][2] = Al[i2]; afl[mt][3] = Al[i3];
            }
#pragma unroll
            for (int nt = 0; nt < 8; nt++) {
                int n = wn + nt * 8 + lr;
                int j0 = SWZ(n, kw0), j1 = SWZ(n, kw0 + 4);
                uint32_t bfh[2] = { Bh[j0], Bh[j1] };
                uint32_t bfl[2] = { Bl[j0], Bl[j1] };
#pragma unroll
                for (int mt = 0; mt < 2; mt++) {
                    mma_f16(acc[mt][nt], afh[mt], bfh);
                    mma_f16(acc[mt][nt], afh[mt], bfl);
                    mma_f16(acc[mt][nt], afl[mt], bfh);
                }
            }
        }
        __syncthreads();
    }

    // epilogue: scale 1/64, add bias, write g_h, fused BN partial stats
    const float inv = 0.015625f;
#pragma unroll
    for (int nt = 0; nt < 8; nt++) {
        int col = n0 + wn + nt * 8 + lc * 2;
        float b0 = __ldg(bias + col), b1 = __ldg(bias + col + 1);
        float s0 = 0.f, s1 = 0.f, q0 = 0.f, q1 = 0.f;
#pragma unroll
        for (int mt = 0; mt < 2; mt++) {
            int row = m0 + wm + mt * 16 + lr;
            float v00 = acc[mt][nt][0] * inv + b0;
            float v01 = acc[mt][nt][1] * inv + b1;
            float v10 = acc[mt][nt][2] * inv + b0;
            float v11 = acc[mt][nt][3] * inv + b1;
            *(float2*)(g_h + (size_t)row * CDIM + col) = make_float2(v00, v01);
            *(float2*)(g_h + (size_t)(row + 8) * CDIM + col) = make_float2(v10, v11);
            s0 += v00 + v10; s1 += v01 + v11;
            q0 = fmaf(v00, v00, q0); q0 = fmaf(v10, v10, q0);
            q1 = fmaf(v01, v01, q1); q1 = fmaf(v11, v11, q1);
        }
#pragma unroll
        for (int off = 4; off < 32; off <<= 1) {
            s0 += __shfl_xor_sync(0xffffffffu, s0, off);
            s1 += __shfl_xor_sync(0xffffffffu, s1, off);
            q0 += __shfl_xor_sync(0xffffffffu, q0, off);
            q1 += __shfl_xor_sync(0xffffffffu, q1, off);
        }
        if (lr == 0) {
            atomicAdd(&g_sum[col], s0);
            atomicAdd(&g_sum[col + 1], s1);
            atomicAdd(&g_sumsq[col], q0);
            atomicAdd(&g_sumsq[col + 1], q1);
        }
    }
}

// ---------------- BN finalize ----------------
__global__ void k_finalize(const float* __restrict__ gamma, const float* __restrict__ beta) {
    int c = threadIdx.x;
    float mu  = g_sum[c] * (1.f / T_TOK);
    float var = g_sumsq[c] * (1.f / T_TOK) - mu * mu;
    float rstd = rsqrtf(var + 1e-5f);
    float sc = gamma[c] * rstd;
    g_scale[c] = sc;
    g_shift[c] = beta[c] - sc * mu;
}

// ---------------- routing ----------------
__global__ __launch_bounds__(256) void k_route(const float* __restrict__ wg2,
                                               const float* __restrict__ bg2) {
    __shared__ float w2s[NE * CDIM];
    __shared__ float scs[CDIM], shs[CDIM];
    __shared__ float s_us[NE];
    int tid = threadIdx.x;
    for (int i = tid; i < NE * CDIM; i += 256) w2s[i] = wg2[i];
    for (int i = tid; i < CDIM; i += 256) { scs[i] = g_scale[i]; shs[i] = g_shift[i]; }
    if (tid < NE) s_us[tid] = 0.f;
    __syncthreads();

    int warp = tid >> 5, lane = tid & 31;
    int tbase = blockIdx.x * 256 + warp * 32;
    for (int it = 0; it < 32; it++) {
        int t = tbase + it;
        const float* hp = g_h + (size_t)t * CDIM;
        float acc[NE];
#pragma unroll
        for (int e = 0; e < NE; e++) acc[e] = 0.f;
#pragma unroll
        for (int i = 0; i < 16; i++) {
            int c = lane + 32 * i;
            float hn = fmaxf(fmaf(hp[c], scs[c], shs[c]), 0.f);
#pragma unroll
            for (int e = 0; e < NE; e++) acc[e] = fmaf(hn, w2s[e * CDIM + c], acc[e]);
        }
#pragma unroll
        for (int e = 0; e < NE; e++)
#pragma unroll
            for (int off = 16; off > 0; off >>= 1)
                acc[e] += __shfl_xor_sync(0xffffffffu, acc[e], off);
        if (lane == 0) {
            float lg[NE];
#pragma unroll
            for (int e = 0; e < NE; e++) lg[e] = acc[e] + bg2[e];
            int i1 = 0; float v1 = lg[0];
#pragma unroll
            for (int e = 1; e < NE; e++) if (lg[e] > v1) { v1 = lg[e]; i1 = e; }
            int i2 = (i1 == 0) ? 1 : 0; float v2 = lg[i2];
#pragma unroll
            for (int e = 0; e < NE; e++)
                if (e != i1 && lg[e] > v2) { v2 = lg[e]; i2 = e; }
            float ew = expf(v2 - v1);
            float invs = 1.f / (1.f + ew);
            float wa = invs, wb = ew * invs;
            g_te[t * 2] = i1; g_te[t * 2 + 1] = i2;
            g_tw[t * 2] = wa; g_tw[t * 2 + 1] = wb;
            atomicAdd(&s_us[i1], wa);
            atomicAdd(&s_us[i2], wb);
        }
    }
    __syncthreads();
    if (tid < NE) atomicAdd(&g_usage[tid], s_us[tid]);
}

// ---------------- expert compute (top-2 only) ----------------
__global__ __launch_bounds__(256) void k_expert(const float* __restrict__ X,
                                                const float* __restrict__ w1,
                                                const float* __restrict__ b1,
                                                const float* __restrict__ w2,
                                                const float* __restrict__ b2) {
    extern __shared__ float smx[];
    float* w1s = smx;
    float* w2s = w1s + CDIM * NH;
    float* b2s = w2s + NH * CDIM;
    float* b1s = b2s + CDIM;
    float* h1s = b1s + NH;
    float* wts = h1s + 64 * NH;
    float* xs  = wts + 256;
    int*   toks = (int*)(xs + 64 * 516);
    __shared__ int s_cnt;

    int e = blockIdx.y;
    int tid = threadIdx.x;
    const float* w1p = w1 + (size_t)e * CDIM * NH;
    const float* w2p = w2 + (size_t)e * NH * CDIM;
    for (int i = tid; i < CDIM * NH; i += 256) { w1s[i] = w1p[i]; w2s[i] = w2p[i]; }
    for (int i = tid; i < CDIM; i += 256) b2s[i] = b2[e * CDIM + i];
    if (tid < NH) b1s[tid] = b1[e * NH + tid];
    if (tid == 0) s_cnt = 0;
    __syncthreads();

    {
        int t = blockIdx.x * 256 + tid;
        int e1 = g_te[t * 2], e2 = g_te[t * 2 + 1];
        float w = (e1 == e) ? g_tw[t * 2] : ((e2 == e) ? g_tw[t * 2 + 1] : -1.f);
        if (w >= 0.f) {
            int p = atomicAdd(&s_cnt, 1);
            toks[p] = t; wts[p] = w;
        }
    }
    __syncthreads();
    int nact = s_cnt;

    for (int bb = 0; bb < nact; bb += 64) {
        int nb = min(64, nact - bb);
        for (int idx = tid; idx < nb * 128; idx += 256) {
            int r = idx >> 7, q = idx & 127;
            float4 v = *(const float4*)(X + (size_t)toks[bb + r] * CDIM + q * 4);
            *(float4*)(xs + r * 516 + q * 4) = v;
        }
        __syncthreads();
        {
            int tl = tid >> 2;
            int hq = (tid & 3) * 4;
            if (tl < nb) {
                float a0 = b1s[hq], a1 = b1s[hq + 1], a2 = b1s[hq + 2], a3 = b1s[hq + 3];
                const float* xr = xs + tl * 516;
#pragma unroll 4
                for (int k = 0; k < CDIM; k++) {
                    float xv = xr[k];
                    float4 w = *(const float4*)(w1s + k * NH + hq);
                    a0 = fmaf(xv, w.x, a0); a1 = fmaf(xv, w.y, a1);
                    a2 = fmaf(xv, w.z, a2); a3 = fmaf(xv, w.w, a3);
                }
                h1s[tl * NH + hq]     = fmaxf(a0, 0.f);
                h1s[tl * NH + hq + 1] = fmaxf(a1, 0.f);
                h1s[tl * NH + hq + 2] = fmaxf(a2, 0.f);
                h1s[tl * NH + hq + 3] = fmaxf(a3, 0.f);
            }
        }
        __syncthreads();
        for (int tl = 0; tl < nb; tl++) {
            int tok = toks[bb + tl];
            float wt = wts[bb + tl];
            float hv[NH];
#pragma unroll
            for (int h = 0; h < NH; h++) hv[h] = h1s[tl * NH + h];
#pragma unroll
            for (int cc = 0; cc < 2; cc++) {
                int c = tid + cc * 256;
                float accv = b2s[c];
#pragma unroll
                for (int h = 0; h < NH; h++)
                    accv = fmaf(hv[h], w2s[h * CDIM + c], accv);
                atomicAdd(&g_of[(size_t)tok * CDIM + c], wt * accv);
            }
        }
        __syncthreads();
    }
}

// ---------------- transpose ----------------
__global__ void k_transpose(float* __restrict__ out) {
    __shared__ float tile[32][33];
    int b = blockIdx.z;
    int n0 = blockIdx.x * 32, c0 = blockIdx.y * 32;
    int tx = threadIdx.x, ty = threadIdx.y;
#pragma unroll
    for (int i = 0; i < 4; i++) {
        int n = n0 + ty + i * 8;
        tile[ty + i * 8][tx] = g_of[(size_t)(b * 4096 + n) * CDIM + c0 + tx];
    }
    __syncthreads();
#pragma unroll
    for (int i = 0; i < 4; i++) {
        int c = c0 + ty + i * 8;
        out[(size_t)(b * CDIM + c) * 4096 + n0 + tx] = tile[tx][ty + i * 8];
    }
}

// ---------------- load-balance loss ----------------
__global__ void k_lb(float* __restrict__ out, int out_size) {
    float lb = 0.f;
    for (int e = 0; e < NE; e++) {
        float u = g_usage[e] * (1.f / T_TOK);
        lb += u * u;
    }
    lb *= (float)NE;
    if (out_size > T_TOK * CDIM) out[T_TOK * CDIM] = lb;
}

// ---------------- launcher ----------------
extern "C" void kernel_launch(void* const* d_in, const int* in_sizes, int n_in,
                              void* d_out, int out_size) {
    const float* x     = (const float*)d_in[0];
    const float* wg1   = (const float*)d_in[1];
    const float* bg1   = (const float*)d_in[2];
    const float* gamma = (const float*)d_in[3];
    const float* beta  = (const float*)d_in[4];
    const float* wg2   = (const float*)d_in[5];
    const float* bg2   = (const float*)d_in[6];
    const float* w1    = (const float*)d_in[7];
    const float* b1    = (const float*)d_in[8];
    const float* w2    = (const float*)d_in[9];
    const float* b2    = (const float*)d_in[10];
    float* out = (float*)d_out;

    k_zero<<<2048, 512>>>();

    int gemm_smem = 2 * STAGE_WORDS * 4;   // 98304 B
    cudaFuncSetAttribute(k_gemm_mma, cudaFuncAttributeMaxDynamicSharedMemorySize, gemm_smem);
    k_gemm_mma<<<dim3(T_TOK / BM, CDIM / BN), 512, gemm_smem>>>(x, wg1, bg1);

    k_finalize<<<1, 512>>>(gamma, beta);
    k_route<<<128, 256>>>(wg2, bg2);

    int smem_bytes = (CDIM * NH + NH * CDIM + CDIM + NH + 64 * NH + 256 + 64 * 516) * 4 + 256 * 4;
    cudaFuncSetAttribute(k_expert, cudaFuncAttributeMaxDynamicSharedMemorySize, smem_bytes);
    k_expert<<<dim3(128, NE), 256, smem_bytes>>>(x, w1, b1, w2, b2);

    k_transpose<<<dim3(128, 16, 8), dim3(32, 8)>>>(out);
    k_lb<<<1, 1>>>(out, out_size);
}

// round 5
// speedup vs baseline: 1.3017x; 1.0970x over previous
#include <cuda_runtime.h>
#include <cuda_fp16.h>
#include <math.h>
#include <stdint.h>

#define T_TOK 32768
#define CDIM  512
#define NE    8
#define NH    16

// GEMM tiling: CTA 128x256, BK=32, 512 threads (16 warps, warp tile 32x64)
#define BM 128
#define BN 256
#define BK 32
#define NSTAGE 16
#define AW (BM * 16)
#define BW (BN * 16)
#define STAGE_WORDS (2 * AW + 2 * BW)

#define SWZ(row, kw) (((row) << 4) + ((kw) ^ ((((row) >> 1) & 3) << 2)))

// ---------------- scratch ----------------
__device__ float g_h [T_TOK * CDIM];
__device__ float g_of2[2][T_TOK][CDIM];   // per-slot expert outputs (no atomics, no zeroing)
__device__ float g_sum[CDIM];
__device__ float g_sumsq[CDIM];
__device__ float g_scale[CDIM];
__device__ float g_shift[CDIM];
__device__ float g_usage[NE];
__device__ int   g_te[T_TOK * 2];
__device__ float g_tw[T_TOK * 2];

// ---------------- helpers ----------------
static __device__ __forceinline__ uint32_t pack2h(float x1, float x0) {
    uint32_t r;
    asm("cvt.rn.f16x2.f32 %0, %1, %2;" : "=r"(r) : "f"(x1), "f"(x0));
    return r;
}
static __device__ __forceinline__ void split4(float4 v, float sc,
                                              uint32_t& h0, uint32_t& h1,
                                              uint32_t& l0, uint32_t& l1) {
    float a = v.x * sc, b = v.y * sc, c = v.z * sc, d = v.w * sc;
    h0 = pack2h(b, a);
    h1 = pack2h(d, c);
    __half2 ha = *(__half2*)&h0;
    __half2 hb = *(__half2*)&h1;
    float2 fa = __half22float2(ha);
    float2 fb = __half22float2(hb);
    l0 = pack2h(b - fa.y, a - fa.x);
    l1 = pack2h(d - fb.y, c - fb.x);
}
static __device__ __forceinline__ void mma_f16(float* d, const uint32_t* a, const uint32_t* b) {
    asm volatile("mma.sync.aligned.m16n8k16.row.col.f32.f16.f16.f32 "
        "{%0,%1,%2,%3},{%4,%5,%6,%7},{%8,%9},{%0,%1,%2,%3};"
        : "+f"(d[0]), "+f"(d[1]), "+f"(d[2]), "+f"(d[3])
        : "r"(a[0]), "r"(a[1]), "r"(a[2]), "r"(a[3]), "r"(b[0]), "r"(b[1]));
}

// ---------------- zero small stats ----------------
__global__ void k_zero() {
    int i = threadIdx.x;
    if (i < CDIM) { g_sum[i] = 0.f; g_sumsq[i] = 0.f; }
    if (i < NE)   g_usage[i] = 0.f;
}

// ---------------- 3xFP16 mma.sync GEMM + fused BN partial stats ----------------
__global__ __launch_bounds__(512, 1) void k_gemm_mma(const float* __restrict__ X,
                                                     const float* __restrict__ W,
                                                     const float* __restrict__ bias) {
    extern __shared__ uint32_t sm[];
    const int m0 = blockIdx.x * BM;
    const int n0 = blockIdx.y * BN;
    const int tid = threadIdx.x;
    const int lane = tid & 31;
    const int wid = tid >> 5;
    const int wm = (wid & 3) * 32;
    const int wn = (wid >> 2) * 64;
    const int lr = lane >> 2, lc = lane & 3;

    const int arow = tid >> 2, aq = tid & 3;
    const int brow = tid >> 1, bq = tid & 1;
    const float* Aptr = X + (size_t)(m0 + arow) * CDIM + aq * 4;
    const float* Bptr = W + (size_t)(n0 + brow) * CDIM + bq * 4;

    float acc[2][8][4];
#pragma unroll
    for (int mt = 0; mt < 2; mt++)
#pragma unroll
        for (int nt = 0; nt < 8; nt++)
#pragma unroll
            for (int q = 0; q < 4; q++) acc[mt][nt][q] = 0.f;

    float4 pa[2], pb[4];
#pragma unroll
    for (int i = 0; i < 2; i++) pa[i] = *(const float4*)(Aptr + 16 * i);
#pragma unroll
    for (int i = 0; i < 4; i++) pb[i] = *(const float4*)(Bptr + 8 * i);

    for (int s = 0; s < NSTAGE; s++) {
        uint32_t* sb = sm + (s & 1) * STAGE_WORDS;
        uint32_t* Ah = sb;
        uint32_t* Al = sb + AW;
        uint32_t* Bh = sb + 2 * AW;
        uint32_t* Bl = sb + 2 * AW + BW;
#pragma unroll
        for (int i = 0; i < 2; i++) {
            uint32_t h0, h1, l0, l1;
            split4(pa[i], 1.0f, h0, h1, l0, l1);
            int sw = SWZ(arow, 2 * (aq + 4 * i));
            *(uint2*)(Ah + sw) = make_uint2(h0, h1);
            *(uint2*)(Al + sw) = make_uint2(l0, l1);
        }
#pragma unroll
        for (int i = 0; i < 4; i++) {
            uint32_t h0, h1, l0, l1;
            split4(pb[i], 64.0f, h0, h1, l0, l1);
            int sw = SWZ(brow, 2 * (bq + 2 * i));
            *(uint2*)(Bh + sw) = make_uint2(h0, h1);
            *(uint2*)(Bl + sw) = make_uint2(l0, l1);
        }
        __syncthreads();
        if (s + 1 < NSTAGE) {
            const float* An = Aptr + (s + 1) * BK;
            const float* Bn = Bptr + (s + 1) * BK;
#pragma unroll
            for (int i = 0; i < 2; i++) pa[i] = *(const float4*)(An + 16 * i);
#pragma unroll
            for (int i = 0; i < 4; i++) pb[i] = *(const float4*)(Bn + 8 * i);
        }
#pragma unroll
        for (int h = 0; h < 2; h++) {
            const int kw0 = h * 8 + lc;
            uint32_t afh[2][4], afl[2][4];
#pragma unroll
            for (int mt = 0; mt < 2; mt++) {
                int m = wm + mt * 16 + lr;
                int i0 = SWZ(m, kw0),     i1 = SWZ(m + 8, kw0);
                int i2 = SWZ(m, kw0 + 4), i3 = SWZ(m + 8, kw0 + 4);
                afh[mt][0] = Ah[i0]; afh[mt][1] = Ah[i1];
                afh[mt][2] = Ah[i2]; afh[mt][3] = Ah[i3];
                afl[mt][0] = Al[i0]; afl[mt][1] = Al[i1];
                afl[mt][2] = Al[i2]; afl[mt][3] = Al[i3];
            }
#pragma unroll
            for (int nt = 0; nt < 8; nt++) {
                int n = wn + nt * 8 + lr;
                int j0 = SWZ(n, kw0), j1 = SWZ(n, kw0 + 4);
                uint32_t bfh[2] = { Bh[j0], Bh[j1] };
                uint32_t bfl[2] = { Bl[j0], Bl[j1] };
#pragma unroll
                for (int mt = 0; mt < 2; mt++) {
                    mma_f16(acc[mt][nt], afh[mt], bfh);
                    mma_f16(acc[mt][nt], afh[mt], bfl);
                    mma_f16(acc[mt][nt], afl[mt], bfh);
                }
            }
        }
        __syncthreads();
    }

    const float inv = 0.015625f;
#pragma unroll
    for (int nt = 0; nt < 8; nt++) {
        int col = n0 + wn + nt * 8 + lc * 2;
        float b0 = __ldg(bias + col), b1 = __ldg(bias + col + 1);
        float s0 = 0.f, s1 = 0.f, q0 = 0.f, q1 = 0.f;
#pragma unroll
        for (int mt = 0; mt < 2; mt++) {
            int row = m0 + wm + mt * 16 + lr;
            float v00 = acc[mt][nt][0] * inv + b0;
            float v01 = acc[mt][nt][1] * inv + b1;
            float v10 = acc[mt][nt][2] * inv + b0;
            float v11 = acc[mt][nt][3] * inv + b1;
            *(float2*)(g_h + (size_t)row * CDIM + col) = make_float2(v00, v01);
            *(float2*)(g_h + (size_t)(row + 8) * CDIM + col) = make_float2(v10, v11);
            s0 += v00 + v10; s1 += v01 + v11;
            q0 = fmaf(v00, v00, q0); q0 = fmaf(v10, v10, q0);
            q1 = fmaf(v01, v01, q1); q1 = fmaf(v11, v11, q1);
        }
#pragma unroll
        for (int off = 4; off < 32; off <<= 1) {
            s0 += __shfl_xor_sync(0xffffffffu, s0, off);
            s1 += __shfl_xor_sync(0xffffffffu, s1, off);
            q0 += __shfl_xor_sync(0xffffffffu, q0, off);
            q1 += __shfl_xor_sync(0xffffffffu, q1, off);
        }
        if (lr == 0) {
            atomicAdd(&g_sum[col], s0);
            atomicAdd(&g_sum[col + 1], s1);
            atomicAdd(&g_sumsq[col], q0);
            atomicAdd(&g_sumsq[col + 1], q1);
        }
    }
}

// ---------------- BN finalize ----------------
__global__ void k_finalize(const float* __restrict__ gamma, const float* __restrict__ beta) {
    int c = threadIdx.x;
    float mu  = g_sum[c] * (1.f / T_TOK);
    float var = g_sumsq[c] * (1.f / T_TOK) - mu * mu;
    float rstd = rsqrtf(var + 1e-5f);
    float sc = gamma[c] * rstd;
    g_scale[c] = sc;
    g_shift[c] = beta[c] - sc * mu;
}

// ---------------- routing: 1024 blocks, 4 tokens per warp ----------------
__global__ __launch_bounds__(256) void k_route(const float* __restrict__ wg2,
                                               const float* __restrict__ bg2) {
    __shared__ float w2s[NE * CDIM];
    __shared__ float scs[CDIM], shs[CDIM];
    __shared__ float s_us[NE];
    int tid = threadIdx.x;
    for (int i = tid; i < NE * CDIM; i += 256) w2s[i] = wg2[i];
    for (int i = tid; i < CDIM; i += 256) { scs[i] = g_scale[i]; shs[i] = g_shift[i]; }
    if (tid < NE) s_us[tid] = 0.f;
    __syncthreads();

    int warp = tid >> 5, lane = tid & 31;
    int tbase = blockIdx.x * 32 + warp * 4;
    for (int it = 0; it < 4; it++) {
        int t = tbase + it;
        const float* hp = g_h + (size_t)t * CDIM;
        float acc[NE];
#pragma unroll
        for (int e = 0; e < NE; e++) acc[e] = 0.f;
#pragma unroll
        for (int i = 0; i < 16; i++) {
            int c = lane + 32 * i;
            float hn = fmaxf(fmaf(hp[c], scs[c], shs[c]), 0.f);
#pragma unroll
            for (int e = 0; e < NE; e++) acc[e] = fmaf(hn, w2s[e * CDIM + c], acc[e]);
        }
#pragma unroll
        for (int e = 0; e < NE; e++)
#pragma unroll
            for (int off = 16; off > 0; off >>= 1)
                acc[e] += __shfl_xor_sync(0xffffffffu, acc[e], off);
        if (lane == 0) {
            float lg[NE];
#pragma unroll
            for (int e = 0; e < NE; e++) lg[e] = acc[e] + bg2[e];
            int i1 = 0; float v1 = lg[0];
#pragma unroll
            for (int e = 1; e < NE; e++) if (lg[e] > v1) { v1 = lg[e]; i1 = e; }
            int i2 = (i1 == 0) ? 1 : 0; float v2 = lg[i2];
#pragma unroll
            for (int e = 0; e < NE; e++)
                if (e != i1 && lg[e] > v2) { v2 = lg[e]; i2 = e; }
            float ew = expf(v2 - v1);
            float invs = 1.f / (1.f + ew);
            float wa = invs, wb = ew * invs;
            g_te[t * 2] = i1; g_te[t * 2 + 1] = i2;
            g_tw[t * 2] = wa; g_tw[t * 2 + 1] = wb;
            atomicAdd(&s_us[i1], wa);
            atomicAdd(&s_us[i2], wb);
        }
    }
    __syncthreads();
    if (tid < NE) atomicAdd(&g_usage[tid], s_us[tid]);
}

// ---------------- expert compute (top-2 only, slot-exclusive stores) ----------------
__global__ __launch_bounds__(256) void k_expert(const float* __restrict__ X,
                                                const float* __restrict__ w1,
                                                const float* __restrict__ b1,
                                                const float* __restrict__ w2,
                                                const float* __restrict__ b2) {
    extern __shared__ float smx[];
    float* w1s = smx;
    float* w2s = w1s + CDIM * NH;
    float* b2s = w2s + NH * CDIM;
    float* b1s = b2s + CDIM;
    float* h1s = b1s + NH;
    float* wts = h1s + 64 * NH;
    float* xs  = wts + 256;
    int*   toks  = (int*)(xs + 64 * 516);
    int*   slots = toks + 256;
    __shared__ int s_cnt;

    int e = blockIdx.y;
    int tid = threadIdx.x;
    const float* w1p = w1 + (size_t)e * CDIM * NH;
    const float* w2p = w2 + (size_t)e * NH * CDIM;
    for (int i = tid; i < CDIM * NH; i += 256) { w1s[i] = w1p[i]; w2s[i] = w2p[i]; }
    for (int i = tid; i < CDIM; i += 256) b2s[i] = b2[e * CDIM + i];
    if (tid < NH) b1s[tid] = b1[e * NH + tid];
    if (tid == 0) s_cnt = 0;
    __syncthreads();

    {
        int t = blockIdx.x * 256 + tid;
        int e1 = g_te[t * 2], e2 = g_te[t * 2 + 1];
        int slot = (e1 == e) ? 0 : ((e2 == e) ? 1 : -1);
        if (slot >= 0) {
            int p = atomicAdd(&s_cnt, 1);
            toks[p] = t;
            slots[p] = slot;
            wts[p] = g_tw[t * 2 + slot];
        }
    }
    __syncthreads();
    int nact = s_cnt;

    for (int bb = 0; bb < nact; bb += 64) {
        int nb = min(64, nact - bb);
        for (int idx = tid; idx < nb * 128; idx += 256) {
            int r = idx >> 7, q = idx & 127;
            float4 v = *(const float4*)(X + (size_t)toks[bb + r] * CDIM + q * 4);
            *(float4*)(xs + r * 516 + q * 4) = v;
        }
        __syncthreads();
        {
            int tl = tid >> 2;
            int hq = (tid & 3) * 4;
            if (tl < nb) {
                float a0 = b1s[hq], a1 = b1s[hq + 1], a2 = b1s[hq + 2], a3 = b1s[hq + 3];
                const float* xr = xs + tl * 516;
#pragma unroll 4
                for (int k = 0; k < CDIM; k++) {
                    float xv = xr[k];
                    float4 w = *(const float4*)(w1s + k * NH + hq);
                    a0 = fmaf(xv, w.x, a0); a1 = fmaf(xv, w.y, a1);
                    a2 = fmaf(xv, w.z, a2); a3 = fmaf(xv, w.w, a3);
                }
                h1s[tl * NH + hq]     = fmaxf(a0, 0.f);
                h1s[tl * NH + hq + 1] = fmaxf(a1, 0.f);
                h1s[tl * NH + hq + 2] = fmaxf(a2, 0.f);
                h1s[tl * NH + hq + 3] = fmaxf(a3, 0.f);
            }
        }
        __syncthreads();
        for (int tl = 0; tl < nb; tl++) {
            int tok = toks[bb + tl];
            int slot = slots[bb + tl];
            float wt = wts[bb + tl];
            float hv[NH];
#pragma unroll
            for (int h = 0; h < NH; h++) hv[h] = h1s[tl * NH + h];
            float* dst = &g_of2[slot][tok][0];
#pragma unroll
            for (int cc = 0; cc < 2; cc++) {
                int c = tid + cc * 256;
                float accv = b2s[c];
#pragma unroll
                for (int h = 0; h < NH; h++)
                    accv = fmaf(hv[h], w2s[h * CDIM + c], accv);
                dst[c] = wt * accv;
            }
        }
        __syncthreads();
    }
}

// ---------------- combine slots + transpose -> out [B, C, N] ----------------
__global__ void k_transpose(float* __restrict__ out) {
    __shared__ float tile[32][33];
    int b = blockIdx.z;
    int n0 = blockIdx.x * 32, c0 = blockIdx.y * 32;
    int tx = threadIdx.x, ty = threadIdx.y;
#pragma unroll
    for (int i = 0; i < 4; i++) {
        int t = b * 4096 + n0 + ty + i * 8;
        tile[ty + i * 8][tx] = g_of2[0][t][c0 + tx] + g_of2[1][t][c0 + tx];
    }
    __syncthreads();
#pragma unroll
    for (int i = 0; i < 4; i++) {
        int c = c0 + ty + i * 8;
        out[(size_t)(b * CDIM + c) * 4096 + n0 + tx] = tile[tx][ty + i * 8];
    }
}

// ---------------- load-balance loss ----------------
__global__ void k_lb(float* __restrict__ out, int out_size) {
    float lb = 0.f;
    for (int e = 0; e < NE; e++) {
        float u = g_usage[e] * (1.f / T_TOK);
        lb += u * u;
    }
    lb *= (float)NE;
    if (out_size > T_TOK * CDIM) out[T_TOK * CDIM] = lb;
}

// ---------------- launcher ----------------
extern "C" void kernel_launch(void* const* d_in, const int* in_sizes, int n_in,
                              void* d_out, int out_size) {
    const float* x     = (const float*)d_in[0];
    const float* wg1   = (const float*)d_in[1];
    const float* bg1   = (const float*)d_in[2];
    const float* gamma = (const float*)d_in[3];
    const float* beta  = (const float*)d_in[4];
    const float* wg2   = (const float*)d_in[5];
    const float* bg2   = (const float*)d_in[6];
    const float* w1    = (const float*)d_in[7];
    const float* b1    = (const float*)d_in[8];
    const float* w2    = (const float*)d_in[9];
    const float* b2    = (const float*)d_in[10];
    float* out = (float*)d_out;

    k_zero<<<1, 512>>>();

    int gemm_smem = 2 * STAGE_WORDS * 4;   // 98304 B
    cudaFuncSetAttribute(k_gemm_mma, cudaFuncAttributeMaxDynamicSharedMemorySize, gemm_smem);
    k_gemm_mma<<<dim3(T_TOK / BM, CDIM / BN), 512, gemm_smem>>>(x, wg1, bg1);

    k_finalize<<<1, 512>>>(gamma, beta);
    k_route<<<1024, 256>>>(wg2, bg2);

    int smem_bytes = (CDIM * NH + NH * CDIM + CDIM + NH + 64 * NH + 256 + 64 * 516) * 4
                     + 512 * 4;  // toks + slots
    cudaFuncSetAttribute(k_expert, cudaFuncAttributeMaxDynamicSharedMemorySize, smem_bytes);
    k_expert<<<dim3(128, NE), 256, smem_bytes>>>(x, w1, b1, w2, b2);

    k_transpose<<<dim3(128, 16, 8), dim3(32, 8)>>>(out);
    k_lb<<<1, 1>>>(out, out_size);
}

// round 6
// speedup vs baseline: 1.4035x; 1.0782x over previous
#include <cuda_runtime.h>
#include <cuda_fp16.h>
#include <math.h>
#include <stdint.h>

#define T_TOK 32768
#define CDIM  512
#define NE    8
#define NH    16

// GEMM tiling: CTA 128x256, BK=32, 512 threads (16 warps, warp tile 32x64)
#define BM 128
#define BN 256
#define BK 32
#define NSTAGE 16
// fp16 stage: Ah 128x16 words (8KB), Al 8KB, Bh 256x16 (16KB), Bl 16KB
#define STAGE_WORDS 12288
#define STAGE_BYTES 49152
#define NBUF 3

#define SWZ(row, kw) (((row) << 4) + ((kw) ^ ((((row) >> 1) & 3) << 2)))

// ---------------- scratch ----------------
__device__ float g_h [T_TOK * CDIM];
__device__ float g_of2[2][T_TOK][CDIM];
__device__ uint32_t g_xh[T_TOK * 256];     // X hi fp16x2, row = 256 words
__device__ uint32_t g_xl[T_TOK * 256];     // X lo
__device__ uint32_t g_wh[CDIM * 256];      // W*64 hi
__device__ uint32_t g_wl[CDIM * 256];      // W*64 lo
__device__ float g_sum[CDIM];
__device__ float g_sumsq[CDIM];
__device__ float g_scale[CDIM];
__device__ float g_shift[CDIM];
__device__ float g_usage[NE];
__device__ int   g_te[T_TOK * 2];
__device__ float g_tw[T_TOK * 2];

// ---------------- helpers ----------------
static __device__ __forceinline__ uint32_t pack2h(float x1, float x0) {
    uint32_t r;
    asm("cvt.rn.f16x2.f32 %0, %1, %2;" : "=r"(r) : "f"(x1), "f"(x0));
    return r;
}
static __device__ __forceinline__ void mma_f16(float* d, const uint32_t* a, const uint32_t* b) {
    asm volatile("mma.sync.aligned.m16n8k16.row.col.f32.f16.f16.f32 "
        "{%0,%1,%2,%3},{%4,%5,%6,%7},{%8,%9},{%0,%1,%2,%3};"
        : "+f"(d[0]), "+f"(d[1]), "+f"(d[2]), "+f"(d[3])
        : "r"(a[0]), "r"(a[1]), "r"(a[2]), "r"(a[3]), "r"(b[0]), "r"(b[1]));
}
static __device__ __forceinline__ uint32_t smem_u32(const void* p) {
    uint32_t a;
    asm("{ .reg .u64 t; cvta.to.shared.u64 t, %1; cvt.u32.u64 %0, t; }" : "=r"(a) : "l"(p));
    return a;
}
static __device__ __forceinline__ void cpa16(uint32_t dst, const void* src) {
    asm volatile("cp.async.cg.shared.global [%0], [%1], 16;" :: "r"(dst), "l"(src));
}
#define CPA_COMMIT() asm volatile("cp.async.commit_group;" ::: "memory")
#define CPA_WAIT2()  asm volatile("cp.async.wait_group 2;" ::: "memory")
#define CPA_WAIT1()  asm volatile("cp.async.wait_group 1;" ::: "memory")
#define CPA_WAIT0()  asm volatile("cp.async.wait_group 0;" ::: "memory")

// ---------------- zero small stats ----------------
__global__ void k_zero() {
    int i = threadIdx.x;
    if (i < CDIM) { g_sum[i] = 0.f; g_sumsq[i] = 0.f; }
    if (i < NE)   g_usage[i] = 0.f;
}

// ---------------- hi/lo fp16 pre-split ----------------
__global__ __launch_bounds__(256) void k_split_x(const float* __restrict__ X) {
    int idx = blockIdx.x * 256 + threadIdx.x;   // float4 index, 4194304 total
    float4 v = ((const float4*)X)[idx];
    uint32_t h0 = pack2h(v.y, v.x), h1 = pack2h(v.w, v.z);
    float2 fa = __half22float2(*(__half2*)&h0);
    float2 fb = __half22float2(*(__half2*)&h1);
    uint32_t l0 = pack2h(v.y - fa.y, v.x - fa.x);
    uint32_t l1 = pack2h(v.w - fb.y, v.z - fb.x);
    ((uint2*)g_xh)[idx] = make_uint2(h0, h1);
    ((uint2*)g_xl)[idx] = make_uint2(l0, l1);
}
__global__ __launch_bounds__(256) void k_split_w(const float* __restrict__ W) {
    int idx = blockIdx.x * 256 + threadIdx.x;   // 65536 total
    float4 v = ((const float4*)W)[idx];
    float a = v.x * 64.f, b = v.y * 64.f, c = v.z * 64.f, d = v.w * 64.f;
    uint32_t h0 = pack2h(b, a), h1 = pack2h(d, c);
    float2 fa = __half22float2(*(__half2*)&h0);
    float2 fb = __half22float2(*(__half2*)&h1);
    uint32_t l0 = pack2h(b - fa.y, a - fa.x);
    uint32_t l1 = pack2h(d - fb.y, c - fb.x);
    ((uint2*)g_wh)[idx] = make_uint2(h0, h1);
    ((uint2*)g_wl)[idx] = make_uint2(l0, l1);
}

// ---------------- 3xFP16 mma.sync GEMM, cp.async 3-stage, no spills ----------------
static __device__ __forceinline__ void issue_stage(int s, uint32_t base, int m0, int n0, int tid) {
    uint32_t st = base + (s % NBUF) * STAGE_BYTES;
    {   // A: 512 chunks hi + 512 lo; thread -> (row, ch)
        int row = tid >> 2, ch = tid & 3;
        uint32_t sw = 4u * (uint32_t)(row * 16 + ((4 * ch) ^ (((row >> 1) & 3) << 2)));
        const uint32_t* sh = g_xh + (size_t)(m0 + row) * 256 + s * 16 + ch * 4;
        const uint32_t* sl = g_xl + (size_t)(m0 + row) * 256 + s * 16 + ch * 4;
        cpa16(st + sw, sh);
        cpa16(st + 8192 + sw, sl);
    }
#pragma unroll
    for (int k = 0; k < 2; k++) {   // B: 1024 chunks hi + 1024 lo
        int cid = tid + 512 * k;
        int row = cid >> 2, ch = cid & 3;
        uint32_t sw = 4u * (uint32_t)(row * 16 + ((4 * ch) ^ (((row >> 1) & 3) << 2)));
        const uint32_t* sh = g_wh + (size_t)(n0 + row) * 256 + s * 16 + ch * 4;
        const uint32_t* sl = g_wl + (size_t)(n0 + row) * 256 + s * 16 + ch * 4;
        cpa16(st + 16384 + sw, sh);
        cpa16(st + 32768 + sw, sl);
    }
}

__global__ __launch_bounds__(512, 1) void k_gemm_mma(const float* __restrict__ bias) {
    extern __shared__ uint32_t sm[];
    const int m0 = blockIdx.x * BM;
    const int n0 = blockIdx.y * BN;
    const int tid = threadIdx.x;
    const int lane = tid & 31;
    const int wid = tid >> 5;
    const int wm = (wid & 3) * 32;
    const int wn = (wid >> 2) * 64;
    const int lr = lane >> 2, lc = lane & 3;
    const uint32_t base = smem_u32(sm);

    float acc[2][8][4];
#pragma unroll
    for (int mt = 0; mt < 2; mt++)
#pragma unroll
        for (int nt = 0; nt < 8; nt++)
#pragma unroll
            for (int q = 0; q < 4; q++) acc[mt][nt][q] = 0.f;

    issue_stage(0, base, m0, n0, tid); CPA_COMMIT();
    issue_stage(1, base, m0, n0, tid); CPA_COMMIT();
    issue_stage(2, base, m0, n0, tid); CPA_COMMIT();

    for (int s = 0; s < NSTAGE; s++) {
        if (s <= 13) CPA_WAIT2();
        else if (s == 14) CPA_WAIT1();
        else CPA_WAIT0();
        __syncthreads();

        uint32_t* sb = sm + (s % NBUF) * STAGE_WORDS;
        uint32_t* Ah = sb;
        uint32_t* Al = sb + 2048;
        uint32_t* Bh = sb + 4096;
        uint32_t* Bl = sb + 8192;
#pragma unroll
        for (int h = 0; h < 2; h++) {
            const int kw0 = h * 8 + lc;
            uint32_t afh[2][4], afl[2][4];
#pragma unroll
            for (int mt = 0; mt < 2; mt++) {
                int m = wm + mt * 16 + lr;
                int i0 = SWZ(m, kw0),     i1 = SWZ(m + 8, kw0);
                int i2 = SWZ(m, kw0 + 4), i3 = SWZ(m + 8, kw0 + 4);
                afh[mt][0] = Ah[i0]; afh[mt][1] = Ah[i1];
                afh[mt][2] = Ah[i2]; afh[mt][3] = Ah[i3];
                afl[mt][0] = Al[i0]; afl[mt][1] = Al[i1];
                afl[mt][2] = Al[i2]; afl[mt][3] = Al[i3];
            }
#pragma unroll
            for (int nt = 0; nt < 8; nt++) {
                int n = wn + nt * 8 + lr;
                int j0 = SWZ(n, kw0), j1 = SWZ(n, kw0 + 4);
                uint32_t bfh[2] = { Bh[j0], Bh[j1] };
                uint32_t bfl[2] = { Bl[j0], Bl[j1] };
#pragma unroll
                for (int mt = 0; mt < 2; mt++) {
                    mma_f16(acc[mt][nt], afh[mt], bfh);
                    mma_f16(acc[mt][nt], afh[mt], bfl);
                    mma_f16(acc[mt][nt], afl[mt], bfh);
                }
            }
        }
        __syncthreads();
        if (s + 3 < NSTAGE) { issue_stage(s + 3, base, m0, n0, tid); CPA_COMMIT(); }
    }

    // epilogue: scale 1/64 (W was x64), add bias, store g_h, fused BN partials
    const float inv = 0.015625f;
#pragma unroll
    for (int nt = 0; nt < 8; nt++) {
        int col = n0 + wn + nt * 8 + lc * 2;
        float b0 = __ldg(bias + col), b1 = __ldg(bias + col + 1);
        float s0 = 0.f, s1 = 0.f, q0 = 0.f, q1 = 0.f;
#pragma unroll
        for (int mt = 0; mt < 2; mt++) {
            int row = m0 + wm + mt * 16 + lr;
            float v00 = acc[mt][nt][0] * inv + b0;
            float v01 = acc[mt][nt][1] * inv + b1;
            float v10 = acc[mt][nt][2] * inv + b0;
            float v11 = acc[mt][nt][3] * inv + b1;
            *(float2*)(g_h + (size_t)row * CDIM + col) = make_float2(v00, v01);
            *(float2*)(g_h + (size_t)(row + 8) * CDIM + col) = make_float2(v10, v11);
            s0 += v00 + v10; s1 += v01 + v11;
            q0 = fmaf(v00, v00, q0); q0 = fmaf(v10, v10, q0);
            q1 = fmaf(v01, v01, q1); q1 = fmaf(v11, v11, q1);
        }
#pragma unroll
        for (int off = 4; off < 32; off <<= 1) {
            s0 += __shfl_xor_sync(0xffffffffu, s0, off);
            s1 += __shfl_xor_sync(0xffffffffu, s1, off);
            q0 += __shfl_xor_sync(0xffffffffu, q0, off);
            q1 += __shfl_xor_sync(0xffffffffu, q1, off);
        }
        if (lr == 0) {
            atomicAdd(&g_sum[col], s0);
            atomicAdd(&g_sum[col + 1], s1);
            atomicAdd(&g_sumsq[col], q0);
            atomicAdd(&g_sumsq[col + 1], q1);
        }
    }
}

// ---------------- BN finalize ----------------
__global__ void k_finalize(const float* __restrict__ gamma, const float* __restrict__ beta) {
    int c = threadIdx.x;
    float mu  = g_sum[c] * (1.f / T_TOK);
    float var = g_sumsq[c] * (1.f / T_TOK) - mu * mu;
    float rstd = rsqrtf(var + 1e-5f);
    float sc = gamma[c] * rstd;
    g_scale[c] = sc;
    g_shift[c] = beta[c] - sc * mu;
}

// ---------------- routing: 2 tokens per warp, grid 2048 ----------------
__global__ __launch_bounds__(256) void k_route(const float* __restrict__ wg2,
                                               const float* __restrict__ bg2) {
    __shared__ float w2s[NE * CDIM];
    __shared__ float scs[CDIM], shs[CDIM];
    __shared__ float s_us[NE];
    int tid = threadIdx.x;
    for (int i = tid; i < NE * CDIM; i += 256) w2s[i] = wg2[i];
    for (int i = tid; i < CDIM; i += 256) { scs[i] = g_scale[i]; shs[i] = g_shift[i]; }
    if (tid < NE) s_us[tid] = 0.f;
    __syncthreads();

    int warp = tid >> 5, lane = tid & 31;
    int t0 = blockIdx.x * 16 + warp * 2;
    int t1 = t0 + 1;
    const float* h0p = g_h + (size_t)t0 * CDIM;
    const float* h1p = g_h + (size_t)t1 * CDIM;
    float a0[NE], a1[NE];
#pragma unroll
    for (int e = 0; e < NE; e++) { a0[e] = 0.f; a1[e] = 0.f; }
#pragma unroll
    for (int i = 0; i < 16; i++) {
        int c = lane + 32 * i;
        float sc = scs[c], sh = shs[c];
        float hn0 = fmaxf(fmaf(h0p[c], sc, sh), 0.f);
        float hn1 = fmaxf(fmaf(h1p[c], sc, sh), 0.f);
#pragma unroll
        for (int e = 0; e < NE; e++) {
            float w = w2s[e * CDIM + c];
            a0[e] = fmaf(hn0, w, a0[e]);
            a1[e] = fmaf(hn1, w, a1[e]);
        }
    }
#pragma unroll
    for (int e = 0; e < NE; e++)
#pragma unroll
        for (int off = 16; off > 0; off >>= 1) {
            a0[e] += __shfl_xor_sync(0xffffffffu, a0[e], off);
            a1[e] += __shfl_xor_sync(0xffffffffu, a1[e], off);
        }
    if (lane == 0) {
#pragma unroll
        for (int tt = 0; tt < 2; tt++) {
            int t = tt ? t1 : t0;
            float* ap = tt ? a1 : a0;
            float lg[NE];
#pragma unroll
            for (int e = 0; e < NE; e++) lg[e] = ap[e] + bg2[e];
            int i1 = 0; float v1 = lg[0];
#pragma unroll
            for (int e = 1; e < NE; e++) if (lg[e] > v1) { v1 = lg[e]; i1 = e; }
            int i2 = (i1 == 0) ? 1 : 0; float v2 = lg[i2];
#pragma unroll
            for (int e = 0; e < NE; e++)
                if (e != i1 && lg[e] > v2) { v2 = lg[e]; i2 = e; }
            float ew = expf(v2 - v1);
            float invs = 1.f / (1.f + ew);
            float wa = invs, wb = ew * invs;
            g_te[t * 2] = i1; g_te[t * 2 + 1] = i2;
            g_tw[t * 2] = wa; g_tw[t * 2 + 1] = wb;
            atomicAdd(&s_us[i1], wa);
            atomicAdd(&s_us[i2], wb);
        }
    }
    __syncthreads();
    if (tid < NE) atomicAdd(&g_usage[tid], s_us[tid]);
}

// ---------------- expert compute (top-2 only, slot-exclusive stores) ----------------
__global__ __launch_bounds__(256) void k_expert(const float* __restrict__ X,
                                                const float* __restrict__ w1,
                                                const float* __restrict__ b1,
                                                const float* __restrict__ w2,
                                                const float* __restrict__ b2) {
    extern __shared__ float smx[];
    float* w1s = smx;
    float* w2s = w1s + CDIM * NH;
    float* b2s = w2s + NH * CDIM;
    float* b1s = b2s + CDIM;
    float* h1s = b1s + NH;
    float* wts = h1s + 64 * NH;
    float* xs  = wts + 256;
    int*   toks  = (int*)(xs + 64 * 516);
    int*   slots = toks + 256;
    __shared__ int s_cnt;

    int e = blockIdx.y;
    int tid = threadIdx.x;
    const float* w1p = w1 + (size_t)e * CDIM * NH;
    const float* w2p = w2 + (size_t)e * NH * CDIM;
    for (int i = tid; i < CDIM * NH; i += 256) { w1s[i] = w1p[i]; w2s[i] = w2p[i]; }
    for (int i = tid; i < CDIM; i += 256) b2s[i] = b2[e * CDIM + i];
    if (tid < NH) b1s[tid] = b1[e * NH + tid];
    if (tid == 0) s_cnt = 0;
    __syncthreads();

    {
        int t = blockIdx.x * 256 + tid;
        int e1 = g_te[t * 2], e2 = g_te[t * 2 + 1];
        int slot = (e1 == e) ? 0 : ((e2 == e) ? 1 : -1);
        if (slot >= 0) {
            int p = atomicAdd(&s_cnt, 1);
            toks[p] = t;
            slots[p] = slot;
            wts[p] = g_tw[t * 2 + slot];
        }
    }
    __syncthreads();
    int nact = s_cnt;

    for (int bb = 0; bb < nact; bb += 64) {
        int nb = min(64, nact - bb);
        for (int idx = tid; idx < nb * 128; idx += 256) {
            int r = idx >> 7, q = idx & 127;
            float4 v = *(const float4*)(X + (size_t)toks[bb + r] * CDIM + q * 4);
            *(float4*)(xs + r * 516 + q * 4) = v;
        }
        __syncthreads();
        {
            int tl = tid >> 2;
            int hq = (tid & 3) * 4;
            if (tl < nb) {
                float a0 = b1s[hq], a1 = b1s[hq + 1], a2 = b1s[hq + 2], a3 = b1s[hq + 3];
                const float* xr = xs + tl * 516;
#pragma unroll 4
                for (int k = 0; k < CDIM; k++) {
                    float xv = xr[k];
                    float4 w = *(const float4*)(w1s + k * NH + hq);
                    a0 = fmaf(xv, w.x, a0); a1 = fmaf(xv, w.y, a1);
                    a2 = fmaf(xv, w.z, a2); a3 = fmaf(xv, w.w, a3);
                }
                h1s[tl * NH + hq]     = fmaxf(a0, 0.f);
                h1s[tl * NH + hq + 1] = fmaxf(a1, 0.f);
                h1s[tl * NH + hq + 2] = fmaxf(a2, 0.f);
                h1s[tl * NH + hq + 3] = fmaxf(a3, 0.f);
            }
        }
        __syncthreads();
        for (int tl = 0; tl < nb; tl++) {
            int tok = toks[bb + tl];
            int slot = slots[bb + tl];
            float wt = wts[bb + tl];
            float hv[NH];
#pragma unroll
            for (int h = 0; h < NH; h++) hv[h] = h1s[tl * NH + h];
            float* dst = &g_of2[slot][tok][0];
#pragma unroll
            for (int cc = 0; cc < 2; cc++) {
                int c = tid + cc * 256;
                float accv = b2s[c];
#pragma unroll
                for (int h = 0; h < NH; h++)
                    accv = fmaf(hv[h], w2s[h * CDIM + c], accv);
                dst[c] = wt * accv;
            }
        }
        __syncthreads();
    }
}

// ---------------- combine slots + transpose -> out [B, C, N] ----------------
__global__ void k_transpose(float* __restrict__ out) {
    __shared__ float tile[32][33];
    int b = blockIdx.z;
    int n0 = blockIdx.x * 32, c0 = blockIdx.y * 32;
    int tx = threadIdx.x, ty = threadIdx.y;
#pragma unroll
    for (int i = 0; i < 4; i++) {
        int t = b * 4096 + n0 + ty + i * 8;
        tile[ty + i * 8][tx] = g_of2[0][t][c0 + tx] + g_of2[1][t][c0 + tx];
    }
    __syncthreads();
#pragma unroll
    for (int i = 0; i < 4; i++) {
        int c = c0 + ty + i * 8;
        out[(size_t)(b * CDIM + c) * 4096 + n0 + tx] = tile[tx][ty + i * 8];
    }
}

// ---------------- load-balance loss ----------------
__global__ void k_lb(float* __restrict__ out, int out_size) {
    float lb = 0.f;
    for (int e = 0; e < NE; e++) {
        float u = g_usage[e] * (1.f / T_TOK);
        lb += u * u;
    }
    lb *= (float)NE;
    if (out_size > T_TOK * CDIM) out[T_TOK * CDIM] = lb;
}

// ---------------- launcher ----------------
extern "C" void kernel_launch(void* const* d_in, const int* in_sizes, int n_in,
                              void* d_out, int out_size) {
    const float* x     = (const float*)d_in[0];
    const float* wg1   = (const float*)d_in[1];
    const float* bg1   = (const float*)d_in[2];
    const float* gamma = (const float*)d_in[3];
    const float* beta  = (const float*)d_in[4];
    const float* wg2   = (const float*)d_in[5];
    const float* bg2   = (const float*)d_in[6];
    const float* w1    = (const float*)d_in[7];
    const float* b1    = (const float*)d_in[8];
    const float* w2    = (const float*)d_in[9];
    const float* b2    = (const float*)d_in[10];
    float* out = (float*)d_out;

    k_zero<<<1, 512>>>();
    k_split_x<<<16384, 256>>>(x);
    k_split_w<<<256, 256>>>(wg1);

    int gemm_smem = NBUF * STAGE_BYTES;   // 147456 B
    cudaFuncSetAttribute(k_gemm_mma, cudaFuncAttributeMaxDynamicSharedMemorySize, gemm_smem);
    k_gemm_mma<<<dim3(T_TOK / BM, CDIM / BN), 512, gemm_smem>>>(bg1);

    k_finalize<<<1, 512>>>(gamma, beta);
    k_route<<<2048, 256>>>(wg2, bg2);

    int smem_bytes = (CDIM * NH + NH * CDIM + CDIM + NH + 64 * NH + 256 + 64 * 516) * 4
                     + 512 * 4;
    cudaFuncSetAttribute(k_expert, cudaFuncAttributeMaxDynamicSharedMemorySize, smem_bytes);
    k_expert<<<dim3(128, NE), 256, smem_bytes>>>(x, w1, b1, w2, b2);

    k_transpose<<<dim3(128, 16, 8), dim3(32, 8)>>>(out);
    k_lb<<<1, 1>>>(out, out_size);
}

// round 7
// speedup vs baseline: 1.8364x; 1.3084x over previous
#include <cuda_runtime.h>
#include <cuda_fp16.h>
#include <math.h>
#include <stdint.h>

#define T_TOK 32768
#define CDIM  512
#define NE    8
#define NH    16

// GEMM tiling: CTA 128x128, BK=32, 256 threads (8 warps: 4m x 2n, warp tile 32x64)
#define BM 128
#define BN 128
#define NSTAGE 16
#define STAGE_WORDS 8192          // Ah 2048 + Al 2048 + Bh 2048 + Bl 2048 words
#define STAGE_BYTES 32768
#define NBUF 3

#define SWZ(row, kw) (((row) << 4) + ((kw) ^ ((((row) >> 1) & 3) << 2)))

// ---------------- scratch ----------------
__device__ float g_h [T_TOK * CDIM];
__device__ float g_of2[2][T_TOK][CDIM];
__device__ uint32_t g_xh[T_TOK * 256];
__device__ uint32_t g_xl[T_TOK * 256];
__device__ uint32_t g_wh[CDIM * 256];
__device__ uint32_t g_wl[CDIM * 256];
__device__ float g_sum[CDIM];
__device__ float g_sumsq[CDIM];
__device__ float g_scale[CDIM];
__device__ float g_shift[CDIM];
__device__ float g_usage[NE];
__device__ int   g_te[T_TOK * 2];
__device__ float g_tw[T_TOK * 2];

// ---------------- helpers ----------------
static __device__ __forceinline__ uint32_t pack2h(float x1, float x0) {
    uint32_t r;
    asm("cvt.rn.f16x2.f32 %0, %1, %2;" : "=r"(r) : "f"(x1), "f"(x0));
    return r;
}
static __device__ __forceinline__ void mma_f16(float* d, const uint32_t* a, uint32_t b0, uint32_t b1) {
    asm volatile("mma.sync.aligned.m16n8k16.row.col.f32.f16.f16.f32 "
        "{%0,%1,%2,%3},{%4,%5,%6,%7},{%8,%9},{%0,%1,%2,%3};"
        : "+f"(d[0]), "+f"(d[1]), "+f"(d[2]), "+f"(d[3])
        : "r"(a[0]), "r"(a[1]), "r"(a[2]), "r"(a[3]), "r"(b0), "r"(b1));
}
static __device__ __forceinline__ void ldsm4(uint32_t* r, uint32_t addr) {
    asm volatile("ldmatrix.sync.aligned.m8n8.x4.shared.b16 {%0,%1,%2,%3}, [%4];"
        : "=r"(r[0]), "=r"(r[1]), "=r"(r[2]), "=r"(r[3]) : "r"(addr));
}
static __device__ __forceinline__ uint32_t smem_u32(const void* p) {
    uint32_t a;
    asm("{ .reg .u64 t; cvta.to.shared.u64 t, %1; cvt.u32.u64 %0, t; }" : "=r"(a) : "l"(p));
    return a;
}
static __device__ __forceinline__ void cpa16(uint32_t dst, const void* src) {
    asm volatile("cp.async.cg.shared.global [%0], [%1], 16;" :: "r"(dst), "l"(src));
}
#define CPA_COMMIT() asm volatile("cp.async.commit_group;" ::: "memory")
#define CPA_WAITN(n) asm volatile("cp.async.wait_group %0;" :: "n"(n) : "memory")

// ---------------- zero small stats ----------------
__global__ void k_zero() {
    int i = threadIdx.x;
    if (i < CDIM) { g_sum[i] = 0.f; g_sumsq[i] = 0.f; }
    if (i < NE)   g_usage[i] = 0.f;
}

// ---------------- hi/lo fp16 pre-split ----------------
__global__ __launch_bounds__(256) void k_split_x(const float* __restrict__ X) {
    int idx = blockIdx.x * 256 + threadIdx.x;
    float4 v = ((const float4*)X)[idx];
    uint32_t h0 = pack2h(v.y, v.x), h1 = pack2h(v.w, v.z);
    float2 fa = __half22float2(*(__half2*)&h0);
    float2 fb = __half22float2(*(__half2*)&h1);
    uint32_t l0 = pack2h(v.y - fa.y, v.x - fa.x);
    uint32_t l1 = pack2h(v.w - fb.y, v.z - fb.x);
    ((uint2*)g_xh)[idx] = make_uint2(h0, h1);
    ((uint2*)g_xl)[idx] = make_uint2(l0, l1);
}
__global__ __launch_bounds__(256) void k_split_w(const float* __restrict__ W) {
    int idx = blockIdx.x * 256 + threadIdx.x;
    float4 v = ((const float4*)W)[idx];
    float a = v.x * 64.f, b = v.y * 64.f, c = v.z * 64.f, d = v.w * 64.f;
    uint32_t h0 = pack2h(b, a), h1 = pack2h(d, c);
    float2 fa = __half22float2(*(__half2*)&h0);
    float2 fb = __half22float2(*(__half2*)&h1);
    uint32_t l0 = pack2h(b - fa.y, a - fa.x);
    uint32_t l1 = pack2h(d - fb.y, c - fb.x);
    ((uint2*)g_wh)[idx] = make_uint2(h0, h1);
    ((uint2*)g_wl)[idx] = make_uint2(l0, l1);
}

// ---------------- GEMM v2: ldmatrix + cp.async, 2 CTAs/SM ----------------
static __device__ __forceinline__ void issue_stage(int s, uint32_t base, int m0, int n0, int tid) {
    uint32_t st = base + (s % NBUF) * STAGE_BYTES;
#pragma unroll
    for (int k = 0; k < 2; k++) {
        int cid = tid + 256 * k;          // 512 chunks per part
        int row = cid >> 2, ch = cid & 3;
        uint32_t sw = 4u * (uint32_t)SWZ(row, 4 * ch);
        const uint32_t* xh = g_xh + (size_t)(m0 + row) * 256 + s * 16 + ch * 4;
        const uint32_t* xl = g_xl + (size_t)(m0 + row) * 256 + s * 16 + ch * 4;
        const uint32_t* wh = g_wh + (size_t)(n0 + row) * 256 + s * 16 + ch * 4;
        const uint32_t* wl = g_wl + (size_t)(n0 + row) * 256 + s * 16 + ch * 4;
        cpa16(st + sw, xh);
        cpa16(st + 8192 + sw, xl);
        cpa16(st + 16384 + sw, wh);
        cpa16(st + 24576 + sw, wl);
    }
}

__global__ __launch_bounds__(256, 2) void k_gemm_mma(const float* __restrict__ bias) {
    extern __shared__ uint32_t sm[];
    const int m0 = blockIdx.x * BM;
    const int n0 = blockIdx.y * BN;
    const int tid = threadIdx.x;
    const int lane = tid & 31;
    const int wid = tid >> 5;
    const int wm = (wid & 3) * 32;       // 4 m-warps
    const int wn = (wid >> 2) * 64;      // 2 n-warps
    const int lr = lane >> 2, lc = lane & 3;
    const uint32_t base = smem_u32(sm);

    // ldmatrix lane geometry (shared by A and B tiles)
    const int lrow8 = (lane & 7) + 8 * ((lane >> 3) & 1);  // row within 16
    const int kwsel = 4 * (lane >> 4);                     // 0 or 4

    float acc[2][8][4];
#pragma unroll
    for (int mt = 0; mt < 2; mt++)
#pragma unroll
        for (int nt = 0; nt < 8; nt++)
#pragma unroll
            for (int q = 0; q < 4; q++) acc[mt][nt][q] = 0.f;

    issue_stage(0, base, m0, n0, tid); CPA_COMMIT();
    issue_stage(1, base, m0, n0, tid); CPA_COMMIT();
    issue_stage(2, base, m0, n0, tid); CPA_COMMIT();

    for (int s = 0; s < NSTAGE; s++) {
        if (s <= 13) CPA_WAITN(2);
        else if (s == 14) CPA_WAITN(1);
        else CPA_WAITN(0);
        __syncthreads();

        uint32_t st = base + (s % NBUF) * STAGE_BYTES;
        uint32_t Ah = st, Al = st + 8192, Bh = st + 16384, Bl = st + 24576;
#pragma unroll
        for (int h = 0; h < 2; h++) {
            const int kw = h * 8 + kwsel;
            uint32_t afh[2][4], afl[2][4];
#pragma unroll
            for (int mt = 0; mt < 2; mt++) {
                int row = wm + mt * 16 + lrow8;
                uint32_t off = 4u * (uint32_t)SWZ(row, kw);
                ldsm4(afh[mt], Ah + off);
                ldsm4(afl[mt], Al + off);
            }
#pragma unroll
            for (int g = 0; g < 4; g++) {
                int row = wn + g * 16 + lrow8;
                uint32_t off = 4u * (uint32_t)SWZ(row, kw);
                uint32_t bfh[4], bfl[4];
                ldsm4(bfh, Bh + off);
                ldsm4(bfl, Bl + off);
#pragma unroll
                for (int mt = 0; mt < 2; mt++) {
                    // sub0: regs {0,2}, sub1: regs {1,3}
                    mma_f16(acc[mt][g * 2],     afh[mt], bfh[0], bfh[2]);
                    mma_f16(acc[mt][g * 2],     afh[mt], bfl[0], bfl[2]);
                    mma_f16(acc[mt][g * 2],     afl[mt], bfh[0], bfh[2]);
                    mma_f16(acc[mt][g * 2 + 1], afh[mt], bfh[1], bfh[3]);
                    mma_f16(acc[mt][g * 2 + 1], afh[mt], bfl[1], bfl[3]);
                    mma_f16(acc[mt][g * 2 + 1], afl[mt], bfh[1], bfh[3]);
                }
            }
        }
        __syncthreads();
        if (s + 3 < NSTAGE) { issue_stage(s + 3, base, m0, n0, tid); CPA_COMMIT(); }
    }

    // epilogue: scale 1/64, add bias, store g_h, fused BN partials
    const float inv = 0.015625f;
#pragma unroll
    for (int nt = 0; nt < 8; nt++) {
        int col = n0 + wn + nt * 8 + lc * 2;
        float b0 = __ldg(bias + col), b1 = __ldg(bias + col + 1);
        float s0 = 0.f, s1 = 0.f, q0 = 0.f, q1 = 0.f;
#pragma unroll
        for (int mt = 0; mt < 2; mt++) {
            int row = m0 + wm + mt * 16 + lr;
            float v00 = acc[mt][nt][0] * inv + b0;
            float v01 = acc[mt][nt][1] * inv + b1;
            float v10 = acc[mt][nt][2] * inv + b0;
            float v11 = acc[mt][nt][3] * inv + b1;
            *(float2*)(g_h + (size_t)row * CDIM + col) = make_float2(v00, v01);
            *(float2*)(g_h + (size_t)(row + 8) * CDIM + col) = make_float2(v10, v11);
            s0 += v00 + v10; s1 += v01 + v11;
            q0 = fmaf(v00, v00, q0); q0 = fmaf(v10, v10, q0);
            q1 = fmaf(v01, v01, q1); q1 = fmaf(v11, v11, q1);
        }
#pragma unroll
        for (int off = 4; off < 32; off <<= 1) {
            s0 += __shfl_xor_sync(0xffffffffu, s0, off);
            s1 += __shfl_xor_sync(0xffffffffu, s1, off);
            q0 += __shfl_xor_sync(0xffffffffu, q0, off);
            q1 += __shfl_xor_sync(0xffffffffu, q1, off);
        }
        if (lr == 0) {
            atomicAdd(&g_sum[col], s0);
            atomicAdd(&g_sum[col + 1], s1);
            atomicAdd(&g_sumsq[col], q0);
            atomicAdd(&g_sumsq[col + 1], q1);
        }
    }
}

// ---------------- BN finalize ----------------
__global__ void k_finalize(const float* __restrict__ gamma, const float* __restrict__ beta) {
    int c = threadIdx.x;
    float mu  = g_sum[c] * (1.f / T_TOK);
    float var = g_sumsq[c] * (1.f / T_TOK) - mu * mu;
    float rstd = rsqrtf(var + 1e-5f);
    float sc = gamma[c] * rstd;
    g_scale[c] = sc;
    g_shift[c] = beta[c] - sc * mu;
}

// ---------------- routing: 2 tokens per warp, grid 2048 ----------------
__global__ __launch_bounds__(256) void k_route(const float* __restrict__ wg2,
                                               const float* __restrict__ bg2) {
    __shared__ float w2s[NE * CDIM];
    __shared__ float scs[CDIM], shs[CDIM];
    __shared__ float s_us[NE];
    int tid = threadIdx.x;
    for (int i = tid; i < NE * CDIM; i += 256) w2s[i] = wg2[i];
    for (int i = tid; i < CDIM; i += 256) { scs[i] = g_scale[i]; shs[i] = g_shift[i]; }
    if (tid < NE) s_us[tid] = 0.f;
    __syncthreads();

    int warp = tid >> 5, lane = tid & 31;
    int t0 = blockIdx.x * 16 + warp * 2;
    int t1 = t0 + 1;
    const float* h0p = g_h + (size_t)t0 * CDIM;
    const float* h1p = g_h + (size_t)t1 * CDIM;
    float a0[NE], a1[NE];
#pragma unroll
    for (int e = 0; e < NE; e++) { a0[e] = 0.f; a1[e] = 0.f; }
#pragma unroll
    for (int i = 0; i < 16; i++) {
        int c = lane + 32 * i;
        float sc = scs[c], sh = shs[c];
        float hn0 = fmaxf(fmaf(h0p[c], sc, sh), 0.f);
        float hn1 = fmaxf(fmaf(h1p[c], sc, sh), 0.f);
#pragma unroll
        for (int e = 0; e < NE; e++) {
            float w = w2s[e * CDIM + c];
            a0[e] = fmaf(hn0, w, a0[e]);
            a1[e] = fmaf(hn1, w, a1[e]);
        }
    }
#pragma unroll
    for (int e = 0; e < NE; e++)
#pragma unroll
        for (int off = 16; off > 0; off >>= 1) {
            a0[e] += __shfl_xor_sync(0xffffffffu, a0[e], off);
            a1[e] += __shfl_xor_sync(0xffffffffu, a1[e], off);
        }
    if (lane == 0) {
#pragma unroll
        for (int tt = 0; tt < 2; tt++) {
            int t = tt ? t1 : t0;
            float* ap = tt ? a1 : a0;
            float lg[NE];
#pragma unroll
            for (int e = 0; e < NE; e++) lg[e] = ap[e] + bg2[e];
            int i1 = 0; float v1 = lg[0];
#pragma unroll
            for (int e = 1; e < NE; e++) if (lg[e] > v1) { v1 = lg[e]; i1 = e; }
            int i2 = (i1 == 0) ? 1 : 0; float v2 = lg[i2];
#pragma unroll
            for (int e = 0; e < NE; e++)
                if (e != i1 && lg[e] > v2) { v2 = lg[e]; i2 = e; }
            float ew = expf(v2 - v1);
            float invs = 1.f / (1.f + ew);
            float wa = invs, wb = ew * invs;
            g_te[t * 2] = i1; g_te[t * 2 + 1] = i2;
            g_tw[t * 2] = wa; g_tw[t * 2 + 1] = wb;
            atomicAdd(&s_us[i1], wa);
            atomicAdd(&s_us[i2], wb);
        }
    }
    __syncthreads();
    if (tid < NE) atomicAdd(&g_usage[tid], s_us[tid]);
}

// ---------------- expert compute v2: registerized w2, 2 blocks/SM ----------------
__global__ __launch_bounds__(256, 2) void k_expert(const float* __restrict__ X,
                                                   const float* __restrict__ w1,
                                                   const float* __restrict__ b1,
                                                   const float* __restrict__ w2,
                                                   const float* __restrict__ b2) {
    extern __shared__ float smx[];
    float* w1s = smx;                      // 512*16 = 8192
    float* b1s = w1s + CDIM * NH;          // 16
    float* h1s = b1s + NH;                 // 32*16 = 512
    float* wts = h1s + 32 * NH;            // 256
    float* xs  = wts + 256;                // 32*516 = 16512
    int*   toks  = (int*)(xs + 32 * 516);  // 256
    int*   slots = toks + 256;             // 256
    __shared__ int s_cnt;

    int e = blockIdx.y;
    int tid = threadIdx.x;
    const float* w1p = w1 + (size_t)e * CDIM * NH;
    for (int i = tid; i < CDIM * NH; i += 256) w1s[i] = w1p[i];
    if (tid < NH) b1s[tid] = b1[e * NH + tid];
    if (tid == 0) s_cnt = 0;

    // registerize w2 columns: thread owns channels 2*tid, 2*tid+1
    float2 w2r[NH];
    const float* w2p = w2 + (size_t)e * NH * CDIM + 2 * tid;
#pragma unroll
    for (int h = 0; h < NH; h++) w2r[h] = *(const float2*)(w2p + h * CDIM);
    float2 b2r = *(const float2*)(b2 + e * CDIM + 2 * tid);
    __syncthreads();

    {
        int t = blockIdx.x * 256 + tid;
        int e1 = g_te[t * 2], e2 = g_te[t * 2 + 1];
        int slot = (e1 == e) ? 0 : ((e2 == e) ? 1 : -1);
        if (slot >= 0) {
            int p = atomicAdd(&s_cnt, 1);
            toks[p] = t;
            slots[p] = slot;
            wts[p] = g_tw[t * 2 + slot];
        }
    }
    __syncthreads();
    int nact = s_cnt;

    for (int bb = 0; bb < nact; bb += 32) {
        int nb = min(32, nact - bb);
        // stage x rows (32 x 512 floats)
        for (int idx = tid; idx < nb * 128; idx += 256) {
            int r = idx >> 7, q = idx & 127;
            float4 v = *(const float4*)(X + (size_t)toks[bb + r] * CDIM + q * 4);
            *(float4*)(xs + r * 516 + q * 4) = v;
        }
        __syncthreads();
        // phase 1: thread = (tl, 2 h-cols)
        {
            int tl = tid >> 3;
            int hp = (tid & 7) * 2;
            if (tl < nb) {
                float a0 = b1s[hp], a1 = b1s[hp + 1];
                const float* xr = xs + tl * 516;
#pragma unroll 8
                for (int k = 0; k < CDIM; k++) {
                    float xv = xr[k];
                    float2 w = *(const float2*)(w1s + k * NH + hp);
                    a0 = fmaf(xv, w.x, a0);
                    a1 = fmaf(xv, w.y, a1);
                }
                h1s[tl * NH + hp]     = fmaxf(a0, 0.f);
                h1s[tl * NH + hp + 1] = fmaxf(a1, 0.f);
            }
        }
        __syncthreads();
        // phase 2: thread = 2 channels, w2 in registers
        for (int tl = 0; tl < nb; tl++) {
            int tok = toks[bb + tl];
            int slot = slots[bb + tl];
            float wt = wts[bb + tl];
            float4 hv0 = *(float4*)(h1s + tl * NH);
            float4 hv1 = *(float4*)(h1s + tl * NH + 4);
            float4 hv2 = *(float4*)(h1s + tl * NH + 8);
            float4 hv3 = *(float4*)(h1s + tl * NH + 12);
            float hv[NH] = { hv0.x, hv0.y, hv0.z, hv0.w, hv1.x, hv1.y, hv1.z, hv1.w,
                             hv2.x, hv2.y, hv2.z, hv2.w, hv3.x, hv3.y, hv3.z, hv3.w };
            float r0 = b2r.x, r1 = b2r.y;
#pragma unroll
            for (int h = 0; h < NH; h++) {
                r0 = fmaf(hv[h], w2r[h].x, r0);
                r1 = fmaf(hv[h], w2r[h].y, r1);
            }
            *(float2*)(&g_of2[slot][tok][2 * tid]) = make_float2(wt * r0, wt * r1);
        }
        __syncthreads();
    }
}

// ---------------- combine slots + transpose -> out [B, C, N] ----------------
__global__ void k_transpose(float* __restrict__ out) {
    __shared__ float tile[32][33];
    int b = blockIdx.z;
    int n0 = blockIdx.x * 32, c0 = blockIdx.y * 32;
    int tx = threadIdx.x, ty = threadIdx.y;
#pragma unroll
    for (int i = 0; i < 4; i++) {
        int t = b * 4096 + n0 + ty + i * 8;
        tile[ty + i * 8][tx] = g_of2[0][t][c0 + tx] + g_of2[1][t][c0 + tx];
    }
    __syncthreads();
#pragma unroll
    for (int i = 0; i < 4; i++) {
        int c = c0 + ty + i * 8;
        out[(size_t)(b * CDIM + c) * 4096 + n0 + tx] = tile[tx][ty + i * 8];
    }
}

// ---------------- load-balance loss ----------------
__global__ void k_lb(float* __restrict__ out, int out_size) {
    float lb = 0.f;
    for (int e = 0; e < NE; e++) {
        float u = g_usage[e] * (1.f / T_TOK);
        lb += u * u;
    }
    lb *= (float)NE;
    if (out_size > T_TOK * CDIM) out[T_TOK * CDIM] = lb;
}

// ---------------- launcher ----------------
extern "C" void kernel_launch(void* const* d_in, const int* in_sizes, int n_in,
                              void* d_out, int out_size) {
    const float* x     = (const float*)d_in[0];
    const float* wg1   = (const float*)d_in[1];
    const float* bg1   = (const float*)d_in[2];
    const float* gamma = (const float*)d_in[3];
    const float* beta  = (const float*)d_in[4];
    const float* wg2   = (const float*)d_in[5];
    const float* bg2   = (const float*)d_in[6];
    const float* w1    = (const float*)d_in[7];
    const float* b1    = (const float*)d_in[8];
    const float* w2    = (const float*)d_in[9];
    const float* b2    = (const float*)d_in[10];
    float* out = (float*)d_out;

    k_zero<<<1, 512>>>();
    k_split_x<<<16384, 256>>>(x);
    k_split_w<<<256, 256>>>(wg1);

    int gemm_smem = NBUF * STAGE_BYTES;   // 98304
    cudaFuncSetAttribute(k_gemm_mma, cudaFuncAttributeMaxDynamicSharedMemorySize, gemm_smem);
    k_gemm_mma<<<dim3(T_TOK / BM, CDIM / BN), 256, gemm_smem>>>(bg1);

    k_finalize<<<1, 512>>>(gamma, beta);
    k_route<<<2048, 256>>>(wg2, bg2);

    int exp_smem = (CDIM * NH + NH + 32 * NH + 256 + 32 * 516) * 4 + 512 * 4;
    cudaFuncSetAttribute(k_expert, cudaFuncAttributeMaxDynamicSharedMemorySize, exp_smem);
    k_expert<<<dim3(128, NE), 256, exp_smem>>>(x, w1, b1, w2, b2);

    k_transpose<<<dim3(128, 16, 8), dim3(32, 8)>>>(out);
    k_lb<<<1, 1>>>(out, out_size);
}

// round 8
// speedup vs baseline: 1.8410x; 1.0025x over previous
#include <cuda_runtime.h>
#include <cuda_fp16.h>
#include <math.h>
#include <stdint.h>

#define T_TOK 32768
#define CDIM  512
#define NE    8
#define NH    16

#define BM 128
#define BN 128
#define NSTAGE 16
#define STAGE_BYTES 32768
#define NBUF 3

#define SWZ(row, kw) (((row) << 4) + ((kw) ^ ((((row) >> 1) & 3) << 2)))

// ---------------- scratch ----------------
__device__ float g_h [T_TOK * CDIM];
__device__ float g_of2[2][T_TOK][CDIM];
__device__ uint32_t g_xh[T_TOK * 256];
__device__ uint32_t g_xl[T_TOK * 256];
__device__ uint32_t g_wh[CDIM * 256];
__device__ uint32_t g_wl[CDIM * 256];
__device__ float g_sum[CDIM];
__device__ float g_sumsq[CDIM];
__device__ float g_scale[CDIM];
__device__ float g_shift[CDIM];
__device__ float g_usage[NE];
__device__ int   g_te[T_TOK * 2];
__device__ float g_tw[T_TOK * 2];

// ---------------- helpers ----------------
static __device__ __forceinline__ uint32_t pack2h(float x1, float x0) {
    uint32_t r;
    asm("cvt.rn.f16x2.f32 %0, %1, %2;" : "=r"(r) : "f"(x1), "f"(x0));
    return r;
}
static __device__ __forceinline__ void mma_f16(float* d, const uint32_t* a, uint32_t b0, uint32_t b1) {
    asm volatile("mma.sync.aligned.m16n8k16.row.col.f32.f16.f16.f32 "
        "{%0,%1,%2,%3},{%4,%5,%6,%7},{%8,%9},{%0,%1,%2,%3};"
        : "+f"(d[0]), "+f"(d[1]), "+f"(d[2]), "+f"(d[3])
        : "r"(a[0]), "r"(a[1]), "r"(a[2]), "r"(a[3]), "r"(b0), "r"(b1));
}
static __device__ __forceinline__ void ldsm4(uint32_t* r, uint32_t addr) {
    asm volatile("ldmatrix.sync.aligned.m8n8.x4.shared.b16 {%0,%1,%2,%3}, [%4];"
        : "=r"(r[0]), "=r"(r[1]), "=r"(r[2]), "=r"(r[3]) : "r"(addr));
}
static __device__ __forceinline__ uint32_t smem_u32(const void* p) {
    uint32_t a;
    asm("{ .reg .u64 t; cvta.to.shared.u64 t, %1; cvt.u32.u64 %0, t; }" : "=r"(a) : "l"(p));
    return a;
}
static __device__ __forceinline__ void cpa16(uint32_t dst, const void* src) {
    asm volatile("cp.async.cg.shared.global [%0], [%1], 16;" :: "r"(dst), "l"(src));
}
#define CPA_COMMIT() asm volatile("cp.async.commit_group;" ::: "memory")
#define CPA_WAITN(n) asm volatile("cp.async.wait_group %0;" :: "n"(n) : "memory")

// ---------------- zero small stats ----------------
__global__ void k_zero() {
    int i = threadIdx.x;
    if (i < CDIM) { g_sum[i] = 0.f; g_sumsq[i] = 0.f; }
    if (i < NE)   g_usage[i] = 0.f;
}

// ---------------- hi/lo fp16 pre-split ----------------
__global__ __launch_bounds__(256) void k_split_x(const float* __restrict__ X) {
    int idx = blockIdx.x * 256 + threadIdx.x;
    float4 v = ((const float4*)X)[idx];
    uint32_t h0 = pack2h(v.y, v.x), h1 = pack2h(v.w, v.z);
    float2 fa = __half22float2(*(__half2*)&h0);
    float2 fb = __half22float2(*(__half2*)&h1);
    uint32_t l0 = pack2h(v.y - fa.y, v.x - fa.x);
    uint32_t l1 = pack2h(v.w - fb.y, v.z - fb.x);
    ((uint2*)g_xh)[idx] = make_uint2(h0, h1);
    ((uint2*)g_xl)[idx] = make_uint2(l0, l1);
}
__global__ __launch_bounds__(256) void k_split_w(const float* __restrict__ W) {
    int idx = blockIdx.x * 256 + threadIdx.x;
    float4 v = ((const float4*)W)[idx];
    float a = v.x * 64.f, b = v.y * 64.f, c = v.z * 64.f, d = v.w * 64.f;
    uint32_t h0 = pack2h(b, a), h1 = pack2h(d, c);
    float2 fa = __half22float2(*(__half2*)&h0);
    float2 fb = __half22float2(*(__half2*)&h1);
    uint32_t l0 = pack2h(b - fa.y, a - fa.x);
    uint32_t l1 = pack2h(d - fb.y, c - fb.x);
    ((uint2*)g_wh)[idx] = make_uint2(h0, h1);
    ((uint2*)g_wl)[idx] = make_uint2(l0, l1);
}

// ---------------- GEMM v3: hoisted addresses, ldmatrix + cp.async ----------------
__global__ __launch_bounds__(256, 2) void k_gemm_mma(const float* __restrict__ bias) {
    extern __shared__ uint32_t sm[];
    const int m0 = blockIdx.x * BM;
    const int n0 = blockIdx.y * BN;
    const int tid = threadIdx.x;
    const int lane = tid & 31;
    const int wid = tid >> 5;
    const int wm = (wid & 3) * 32;
    const int wn = (wid >> 2) * 64;
    const int lr = lane >> 2, lc = lane & 3;
    const uint32_t base = smem_u32(sm);

    // ---- hoisted loader addressing: thread covers rows (tid>>2) and (tid>>2)+64, chunk tid&3
    const int ldrow = tid >> 2, ldch = tid & 3;
    const uint32_t swd = 4u * (uint32_t)SWZ(ldrow, 4 * ldch);         // dst for row ldrow
    const uint32_t swd2 = 4u * (uint32_t)SWZ(ldrow + 64, 4 * ldch);   // dst for row ldrow+64
    const uint32_t* pxh = g_xh + (size_t)(m0 + ldrow) * 256 + ldch * 4;
    const uint32_t* pxl = g_xl + (size_t)(m0 + ldrow) * 256 + ldch * 4;
    const uint32_t* pwh = g_wh + (size_t)(n0 + ldrow) * 256 + ldch * 4;
    const uint32_t* pwl = g_wl + (size_t)(n0 + ldrow) * 256 + ldch * 4;
    const int rstep = 64 * 256;     // +64 rows in words

    // ---- hoisted ldmatrix offsets
    const int lrow8 = (lane & 7) + 8 * ((lane >> 3) & 1);
    const int kwsel = 4 * (lane >> 4);
    uint32_t aoffs[2][2], boffs[2][4];
#pragma unroll
    for (int h = 0; h < 2; h++) {
        int kw = h * 8 + kwsel;
#pragma unroll
        for (int mt = 0; mt < 2; mt++)
            aoffs[h][mt] = 4u * (uint32_t)SWZ(wm + mt * 16 + lrow8, kw);
#pragma unroll
        for (int g = 0; g < 4; g++)
            boffs[h][g] = 4u * (uint32_t)SWZ(wn + g * 16 + lrow8, kw) + 16384u;
    }

    float acc[2][8][4];
#pragma unroll
    for (int mt = 0; mt < 2; mt++)
#pragma unroll
        for (int nt = 0; nt < 8; nt++)
#pragma unroll
            for (int q = 0; q < 4; q++) acc[mt][nt][q] = 0.f;

#pragma unroll
    for (int s = 0; s < NBUF; s++) {
        uint32_t st = base + s * STAGE_BYTES;
        const uint32_t* sx = pxh + s * 16;
        cpa16(st + swd, sx);
        cpa16(st + swd2, sx + rstep);
        sx = pxl + s * 16;
        cpa16(st + 8192 + swd, sx);
        cpa16(st + 8192 + swd2, sx + rstep);
        sx = pwh + s * 16;
        cpa16(st + 16384 + swd, sx);
        cpa16(st + 16384 + swd2, sx + rstep);
        sx = pwl + s * 16;
        cpa16(st + 24576 + swd, sx);
        cpa16(st + 24576 + swd2, sx + rstep);
        CPA_COMMIT();
    }

    for (int s = 0; s < NSTAGE; s++) {
        if (s <= 13) CPA_WAITN(2);
        else if (s == 14) CPA_WAITN(1);
        else CPA_WAITN(0);
        __syncthreads();

        uint32_t st = base + (s % NBUF) * STAGE_BYTES;
#pragma unroll
        for (int h = 0; h < 2; h++) {
            uint32_t afh[2][4], afl[2][4];
#pragma unroll
            for (int mt = 0; mt < 2; mt++) {
                ldsm4(afh[mt], st + aoffs[h][mt]);
                ldsm4(afl[mt], st + 8192 + aoffs[h][mt]);
            }
#pragma unroll
            for (int g = 0; g < 4; g++) {
                uint32_t bfh[4], bfl[4];
                ldsm4(bfh, st + boffs[h][g]);
                ldsm4(bfl, st + 8192 + boffs[h][g]);
#pragma unroll
                for (int mt = 0; mt < 2; mt++) {
                    mma_f16(acc[mt][g * 2],     afh[mt], bfh[0], bfh[2]);
                    mma_f16(acc[mt][g * 2],     afh[mt], bfl[0], bfl[2]);
                    mma_f16(acc[mt][g * 2],     afl[mt], bfh[0], bfh[2]);
                    mma_f16(acc[mt][g * 2 + 1], afh[mt], bfh[1], bfh[3]);
                    mma_f16(acc[mt][g * 2 + 1], afh[mt], bfl[1], bfl[3]);
                    mma_f16(acc[mt][g * 2 + 1], afl[mt], bfh[1], bfh[3]);
                }
            }
        }
        __syncthreads();
        if (s + 3 < NSTAGE) {
            int sn = s + 3;
            uint32_t st2 = base + (sn % NBUF) * STAGE_BYTES;
            const uint32_t* sx = pxh + sn * 16;
            cpa16(st2 + swd, sx);
            cpa16(st2 + swd2, sx + rstep);
            sx = pxl + sn * 16;
            cpa16(st2 + 8192 + swd, sx);
            cpa16(st2 + 8192 + swd2, sx + rstep);
            sx = pwh + sn * 16;
            cpa16(st2 + 16384 + swd, sx);
            cpa16(st2 + 16384 + swd2, sx + rstep);
            sx = pwl + sn * 16;
            cpa16(st2 + 24576 + swd, sx);
            cpa16(st2 + 24576 + swd2, sx + rstep);
            CPA_COMMIT();
        }
    }

    // epilogue
    const float inv = 0.015625f;
#pragma unroll
    for (int nt = 0; nt < 8; nt++) {
        int col = n0 + wn + nt * 8 + lc * 2;
        float b0 = __ldg(bias + col), b1 = __ldg(bias + col + 1);
        float s0 = 0.f, s1 = 0.f, q0 = 0.f, q1 = 0.f;
#pragma unroll
        for (int mt = 0; mt < 2; mt++) {
            int row = m0 + wm + mt * 16 + lr;
            float v00 = acc[mt][nt][0] * inv + b0;
            float v01 = acc[mt][nt][1] * inv + b1;
            float v10 = acc[mt][nt][2] * inv + b0;
            float v11 = acc[mt][nt][3] * inv + b1;
            *(float2*)(g_h + (size_t)row * CDIM + col) = make_float2(v00, v01);
            *(float2*)(g_h + (size_t)(row + 8) * CDIM + col) = make_float2(v10, v11);
            s0 += v00 + v10; s1 += v01 + v11;
            q0 = fmaf(v00, v00, q0); q0 = fmaf(v10, v10, q0);
            q1 = fmaf(v01, v01, q1); q1 = fmaf(v11, v11, q1);
        }
#pragma unroll
        for (int off = 4; off < 32; off <<= 1) {
            s0 += __shfl_xor_sync(0xffffffffu, s0, off);
            s1 += __shfl_xor_sync(0xffffffffu, s1, off);
            q0 += __shfl_xor_sync(0xffffffffu, q0, off);
            q1 += __shfl_xor_sync(0xffffffffu, q1, off);
        }
        if (lr == 0) {
            atomicAdd(&g_sum[col], s0);
            atomicAdd(&g_sum[col + 1], s1);
            atomicAdd(&g_sumsq[col], q0);
            atomicAdd(&g_sumsq[col + 1], q1);
        }
    }
}

// ---------------- BN finalize ----------------
__global__ void k_finalize(const float* __restrict__ gamma, const float* __restrict__ beta) {
    int c = threadIdx.x;
    float mu  = g_sum[c] * (1.f / T_TOK);
    float var = g_sumsq[c] * (1.f / T_TOK) - mu * mu;
    float rstd = rsqrtf(var + 1e-5f);
    float sc = gamma[c] * rstd;
    g_scale[c] = sc;
    g_shift[c] = beta[c] - sc * mu;
}

// ---------------- routing: 2 tokens per warp, grid 2048 ----------------
__global__ __launch_bounds__(256) void k_route(const float* __restrict__ wg2,
                                               const float* __restrict__ bg2) {
    __shared__ float w2s[NE * CDIM];
    __shared__ float scs[CDIM], shs[CDIM];
    __shared__ float s_us[NE];
    int tid = threadIdx.x;
    for (int i = tid; i < NE * CDIM; i += 256) w2s[i] = wg2[i];
    for (int i = tid; i < CDIM; i += 256) { scs[i] = g_scale[i]; shs[i] = g_shift[i]; }
    if (tid < NE) s_us[tid] = 0.f;
    __syncthreads();

    int warp = tid >> 5, lane = tid & 31;
    int t0 = blockIdx.x * 16 + warp * 2;
    int t1 = t0 + 1;
    const float* h0p = g_h + (size_t)t0 * CDIM;
    const float* h1p = g_h + (size_t)t1 * CDIM;
    float a0[NE], a1[NE];
#pragma unroll
    for (int e = 0; e < NE; e++) { a0[e] = 0.f; a1[e] = 0.f; }
#pragma unroll
    for (int i = 0; i < 16; i++) {
        int c = lane + 32 * i;
        float sc = scs[c], sh = shs[c];
        float hn0 = fmaxf(fmaf(h0p[c], sc, sh), 0.f);
        float hn1 = fmaxf(fmaf(h1p[c], sc, sh), 0.f);
#pragma unroll
        for (int e = 0; e < NE; e++) {
            float w = w2s[e * CDIM + c];
            a0[e] = fmaf(hn0, w, a0[e]);
            a1[e] = fmaf(hn1, w, a1[e]);
        }
    }
#pragma unroll
    for (int e = 0; e < NE; e++)
#pragma unroll
        for (int off = 16; off > 0; off >>= 1) {
            a0[e] += __shfl_xor_sync(0xffffffffu, a0[e], off);
            a1[e] += __shfl_xor_sync(0xffffffffu, a1[e], off);
        }
    if (lane == 0) {
#pragma unroll
        for (int tt = 0; tt < 2; tt++) {
            int t = tt ? t1 : t0;
            float* ap = tt ? a1 : a0;
            float lg[NE];
#pragma unroll
            for (int e = 0; e < NE; e++) lg[e] = ap[e] + bg2[e];
            int i1 = 0; float v1 = lg[0];
#pragma unroll
            for (int e = 1; e < NE; e++) if (lg[e] > v1) { v1 = lg[e]; i1 = e; }
            int i2 = (i1 == 0) ? 1 : 0; float v2 = lg[i2];
#pragma unroll
            for (int e = 0; e < NE; e++)
                if (e != i1 && lg[e] > v2) { v2 = lg[e]; i2 = e; }
            float ew = expf(v2 - v1);
            float invs = 1.f / (1.f + ew);
            float wa = invs, wb = ew * invs;
            g_te[t * 2] = i1; g_te[t * 2 + 1] = i2;
            g_tw[t * 2] = wa; g_tw[t * 2 + 1] = wb;
            atomicAdd(&s_us[i1], wa);
            atomicAdd(&s_us[i2], wb);
        }
    }
    __syncthreads();
    if (tid < NE) atomicAdd(&g_usage[tid], s_us[tid]);
}

// ---------------- expert compute v2 ----------------
__global__ __launch_bounds__(256, 2) void k_expert(const float* __restrict__ X,
                                                   const float* __restrict__ w1,
                                                   const float* __restrict__ b1,
                                                   const float* __restrict__ w2,
                                                   const float* __restrict__ b2) {
    extern __shared__ float smx[];
    float* w1s = smx;
    float* b1s = w1s + CDIM * NH;
    float* h1s = b1s + NH;
    float* wts = h1s + 32 * NH;
    float* xs  = wts + 256;
    int*   toks  = (int*)(xs + 32 * 516);
    int*   slots = toks + 256;
    __shared__ int s_cnt;

    int e = blockIdx.y;
    int tid = threadIdx.x;
    const float* w1p = w1 + (size_t)e * CDIM * NH;
    for (int i = tid; i < CDIM * NH; i += 256) w1s[i] = w1p[i];
    if (tid < NH) b1s[tid] = b1[e * NH + tid];
    if (tid == 0) s_cnt = 0;

    float2 w2r[NH];
    const float* w2p = w2 + (size_t)e * NH * CDIM + 2 * tid;
#pragma unroll
    for (int h = 0; h < NH; h++) w2r[h] = *(const float2*)(w2p + h * CDIM);
    float2 b2r = *(const float2*)(b2 + e * CDIM + 2 * tid);
    __syncthreads();

    {
        int t = blockIdx.x * 256 + tid;
        int e1 = g_te[t * 2], e2 = g_te[t * 2 + 1];
        int slot = (e1 == e) ? 0 : ((e2 == e) ? 1 : -1);
        if (slot >= 0) {
            int p = atomicAdd(&s_cnt, 1);
            toks[p] = t;
            slots[p] = slot;
            wts[p] = g_tw[t * 2 + slot];
        }
    }
    __syncthreads();
    int nact = s_cnt;

    for (int bb = 0; bb < nact; bb += 32) {
        int nb = min(32, nact - bb);
        for (int idx = tid; idx < nb * 128; idx += 256) {
            int r = idx >> 7, q = idx & 127;
            float4 v = *(const float4*)(X + (size_t)toks[bb + r] * CDIM + q * 4);
            *(float4*)(xs + r * 516 + q * 4) = v;
        }
        __syncthreads();
        {
            int tl = tid >> 3;
            int hp = (tid & 7) * 2;
            if (tl < nb) {
                float a0 = b1s[hp], a1 = b1s[hp + 1];
                const float* xr = xs + tl * 516;
#pragma unroll 8
                for (int k = 0; k < CDIM; k++) {
                    float xv = xr[k];
                    float2 w = *(const float2*)(w1s + k * NH + hp);
                    a0 = fmaf(xv, w.x, a0);
                    a1 = fmaf(xv, w.y, a1);
                }
                h1s[tl * NH + hp]     = fmaxf(a0, 0.f);
                h1s[tl * NH + hp + 1] = fmaxf(a1, 0.f);
            }
        }
        __syncthreads();
        for (int tl = 0; tl < nb; tl++) {
            int tok = toks[bb + tl];
            int slot = slots[bb + tl];
            float wt = wts[bb + tl];
            float4 hv0 = *(float4*)(h1s + tl * NH);
            float4 hv1 = *(float4*)(h1s + tl * NH + 4);
            float4 hv2 = *(float4*)(h1s + tl * NH + 8);
            float4 hv3 = *(float4*)(h1s + tl * NH + 12);
            float hv[NH] = { hv0.x, hv0.y, hv0.z, hv0.w, hv1.x, hv1.y, hv1.z, hv1.w,
                             hv2.x, hv2.y, hv2.z, hv2.w, hv3.x, hv3.y, hv3.z, hv3.w };
            float r0 = b2r.x, r1 = b2r.y;
#pragma unroll
            for (int h = 0; h < NH; h++) {
                r0 = fmaf(hv[h], w2r[h].x, r0);
                r1 = fmaf(hv[h], w2r[h].y, r1);
            }
            *(float2*)(&g_of2[slot][tok][2 * tid]) = make_float2(wt * r0, wt * r1);
        }
        __syncthreads();
    }
}

// ---------------- combine + transpose ----------------
__global__ void k_transpose(float* __restrict__ out) {
    __shared__ float tile[32][33];
    int b = blockIdx.z;
    int n0 = blockIdx.x * 32, c0 = blockIdx.y * 32;
    int tx = threadIdx.x, ty = threadIdx.y;
#pragma unroll
    for (int i = 0; i < 4; i++) {
        int t = b * 4096 + n0 + ty + i * 8;
        tile[ty + i * 8][tx] = g_of2[0][t][c0 + tx] + g_of2[1][t][c0 + tx];
    }
    __syncthreads();
#pragma unroll
    for (int i = 0; i < 4; i++) {
        int c = c0 + ty + i * 8;
        out[(size_t)(b * CDIM + c) * 4096 + n0 + tx] = tile[tx][ty + i * 8];
    }
}

// ---------------- load-balance loss ----------------
__global__ void k_lb(float* __restrict__ out, int out_size) {
    float lb = 0.f;
    for (int e = 0; e < NE; e++) {
        float u = g_usage[e] * (1.f / T_TOK);
        lb += u * u;
    }
    lb *= (float)NE;
    if (out_size > T_TOK * CDIM) out[T_TOK * CDIM] = lb;
}

// ---------------- launcher ----------------
extern "C" void kernel_launch(void* const* d_in, const int* in_sizes, int n_in,
                              void* d_out, int out_size) {
    const float* x     = (const float*)d_in[0];
    const float* wg1   = (const float*)d_in[1];
    const float* bg1   = (const float*)d_in[2];
    const float* gamma = (const float*)d_in[3];
    const float* beta  = (const float*)d_in[4];
    const float* wg2   = (const float*)d_in[5];
    const float* bg2   = (const float*)d_in[6];
    const float* w1    = (const float*)d_in[7];
    const float* b1    = (const float*)d_in[8];
    const float* w2    = (const float*)d_in[9];
    const float* b2    = (const float*)d_in[10];
    float* out = (float*)d_out;

    k_zero<<<1, 512>>>();
    k_split_x<<<16384, 256>>>(x);
    k_split_w<<<256, 256>>>(wg1);

    int gemm_smem = NBUF * STAGE_BYTES;
    cudaFuncSetAttribute(k_gemm_mma, cudaFuncAttributeMaxDynamicSharedMemorySize, gemm_smem);
    k_gemm_mma<<<dim3(T_TOK / BM, CDIM / BN), 256, gemm_smem>>>(bg1);

    k_finalize<<<1, 512>>>(gamma, beta);
    k_route<<<2048, 256>>>(wg2, bg2);

    int exp_smem = (CDIM * NH + NH + 32 * NH + 256 + 32 * 516) * 4 + 512 * 4;
    cudaFuncSetAttribute(k_expert, cudaFuncAttributeMaxDynamicSharedMemorySize, exp_smem);
    k_expert<<<dim3(128, NE), 256, exp_smem>>>(x, w1, b1, w2, b2);

    k_transpose<<<dim3(128, 16, 8), dim3(32, 8)>>>(out);
    k_lb<<<1, 1>>>(out, out_size);
}